// round 5
// baseline (speedup 1.0000x reference)
#include <cuda_runtime.h>

#define BATCH 2
#define NSEQ  2048
#define DIMM  1024
#define NH    8
#define DH    64
#define NE    8
#define TTOK  (BATCH*NSEQ)     /* 4096 tokens */
#define BH    (BATCH*NH)       /* 16 */
#define GCOLS (NH*NE)          /* 64 gate columns */
#define KSPLIT 4
#define KCH   (DIMM/KSPLIT)    /* 256 */

// ---------------- scratch (static device globals; allowed) ----------------
static __device__ float g_q[BH*NSEQ*DH];
static __device__ float g_k[BH*NSEQ*DH];
static __device__ float g_glogit[TTOK*GCOLS];
static __device__ float g_gate[BH*NSEQ];
static __device__ int   g_cnt[NH*NE];
static __device__ int   g_list[NH*NE*TTOK];
static __device__ float g_vpart[KSPLIT][BH*NSEQ*DH];   // split-K partials (32MB)
static __device__ float g_vals[BH*NSEQ*DH];
static __device__ float g_attn[BH*NSEQ*DH];
static __device__ float g_outh[(size_t)BH*NSEQ*DIMM];

__global__ void init_kernel() {
    int i = threadIdx.x;
    if (i < NH*NE) g_cnt[i] = 0;
}

// ---------------- kernel 1: fused QK+gate projection GEMM ----------------
// X(4096x1024) @ [Wq|Wk|Wgate](1024x1088). 128x128 tile, 256 thr, 8x8 micro,
// double-buffered K-chunks of 8.
__global__ void __launch_bounds__(256, 2)
proj_kernel(const float* __restrict__ x,
            const float* __restrict__ wq,
            const float* __restrict__ wk,
            const float* __restrict__ wg) {
    __shared__ float As[2][8][128];   // [k][m]
    __shared__ float Bs[2][8][128];   // [k][n]
    int tid = threadIdx.x;
    int bm = blockIdx.x, bn = blockIdx.y;

    int la_row = tid >> 1;            // 0..127
    int la_k   = (tid & 1) * 4;       // 0 | 4
    const float* aptr = x + (size_t)(bm*128 + la_row)*DIMM + la_k;

    int lb_k = tid >> 5;              // 0..7
    int lb_n = (tid & 31) * 4;        // 0..124
    int gc   = bn*128 + lb_n;         // global col (float4 never straddles segs)

    int tyy = tid >> 4, txx = tid & 15;
    float acc[8][8] = {};
    float4 pa, pb;

    pa = *(const float4*)(aptr + 0);
    {
        int krow = lb_k;
        if (gc < 512)       pb = *(const float4*)&wq[(size_t)krow*512 + gc];
        else if (gc < 1024) pb = *(const float4*)&wk[(size_t)krow*512 + gc - 512];
        else if (gc < 1088) pb = *(const float4*)&wg[(size_t)krow*64  + gc - 1024];
        else                pb = make_float4(0.f,0.f,0.f,0.f);
    }
    As[0][la_k+0][la_row] = pa.x; As[0][la_k+1][la_row] = pa.y;
    As[0][la_k+2][la_row] = pa.z; As[0][la_k+3][la_row] = pa.w;
    *(float4*)&Bs[0][lb_k][lb_n] = pb;
    __syncthreads();

    const int NC = DIMM/8;
    for (int c = 0; c < NC; c++) {
        int cur = c & 1;
        if (c + 1 < NC) {
            int k0 = (c + 1) * 8;
            pa = *(const float4*)(aptr + k0);
            int krow = k0 + lb_k;
            if (gc < 512)       pb = *(const float4*)&wq[(size_t)krow*512 + gc];
            else if (gc < 1024) pb = *(const float4*)&wk[(size_t)krow*512 + gc - 512];
            else if (gc < 1088) pb = *(const float4*)&wg[(size_t)krow*64  + gc - 1024];
            else                pb = make_float4(0.f,0.f,0.f,0.f);
        }
#pragma unroll
        for (int kk = 0; kk < 8; kk++) {
            float4 a0 = *(const float4*)&As[cur][kk][tyy*8];
            float4 a1 = *(const float4*)&As[cur][kk][tyy*8+4];
            float4 b0 = *(const float4*)&Bs[cur][kk][txx*8];
            float4 b1 = *(const float4*)&Bs[cur][kk][txx*8+4];
            float av[8] = {a0.x,a0.y,a0.z,a0.w,a1.x,a1.y,a1.z,a1.w};
            float bv[8] = {b0.x,b0.y,b0.z,b0.w,b1.x,b1.y,b1.z,b1.w};
#pragma unroll
            for (int i = 0; i < 8; i++)
#pragma unroll
                for (int j = 0; j < 8; j++)
                    acc[i][j] += av[i] * bv[j];
        }
        if (c + 1 < NC) {
            int nxt = cur ^ 1;
            __syncthreads();
            As[nxt][la_k+0][la_row] = pa.x; As[nxt][la_k+1][la_row] = pa.y;
            As[nxt][la_k+2][la_row] = pa.z; As[nxt][la_k+3][la_row] = pa.w;
            *(float4*)&Bs[nxt][lb_k][lb_n] = pb;
            __syncthreads();
        }
    }
#pragma unroll
    for (int i = 0; i < 8; i++) {
        int row = bm*128 + tyy*8 + i;
        int b_ = row >> 11, n = row & 2047;
#pragma unroll
        for (int j = 0; j < 8; j++) {
            int c = bn*128 + txx*8 + j;
            float v = acc[i][j];
            if (c < 512) {
                g_q[((size_t)(b_*NH + (c >> 6))*NSEQ + n)*DH + (c & 63)] = v;
            } else if (c < 1024) {
                int c2 = c - 512;
                g_k[((size_t)(b_*NH + (c2 >> 6))*NSEQ + n)*DH + (c2 & 63)] = v;
            } else if (c < 1088) {
                g_glogit[(size_t)row*GCOLS + (c - 1024)] = v;
            }
        }
    }
}

// ---------------- kernel 2: gate sigmoid + argmax + bucket append ----------------
__global__ void gate_kernel() {
    int id = blockIdx.x * blockDim.x + threadIdx.x;
    if (id >= TTOK*NH) return;
    int t = id / NH, h = id % NH;
    const float* lg = &g_glogit[(size_t)t*GCOLS + h*NE];
    float best = lg[0]; int be = 0;
#pragma unroll
    for (int e = 1; e < NE; e++) { float v = lg[e]; if (v > best) { best = v; be = e; } }
    float gate = 1.f / (1.f + __expf(-best));
    int b_ = t >> 11, n = t & 2047;
    g_gate[(size_t)(b_*NH + h)*NSEQ + n] = gate;
    int pos = atomicAdd(&g_cnt[h*NE + be], 1);
    g_list[(size_t)(h*NE + be)*TTOK + pos] = t;
}

// ---------------- kernel 3: grouped value-expert GEMM, split-K x4 ----------------
// per (h,e,z): gather X(tok x 256) @ W_eh(256x64) -> g_vpart[z]
__global__ void __launch_bounds__(128, 4)
value_kernel(const float* __restrict__ x,
             const float* __restrict__ vexp) {
    __shared__ float As[2][8][128];
    __shared__ float Bs[2][8][64];
    __shared__ int   ts[128];
    int he = blockIdx.x; int h = he >> 3, e = he & 7;
    int cnt = g_cnt[he];
    int start = blockIdx.y * 128;
    if (start >= cnt) return;
    int z = blockIdx.z;
    int kbase = z * KCH;
    int tid = threadIdx.x;
    ts[tid] = (start + tid < cnt) ? g_list[(size_t)he*TTOK + start + tid] : -1;
    __syncthreads();
    const float* W = vexp + (size_t)(e*NH + h)*DIMM*DH + (size_t)kbase*DH;
    int at = ts[tid];
    const float* aptr = x + (size_t)(at >= 0 ? at : 0)*DIMM + kbase;
    int lb_k = tid >> 4, lb_n = (tid & 15) * 4;
    int tyy = tid >> 3, txx = tid & 7;
    float acc[8][8] = {};
    float4 pa0, pa1, pb;

    if (at >= 0) { pa0 = *(const float4*)(aptr + 0); pa1 = *(const float4*)(aptr + 4); }
    else { pa0 = pa1 = make_float4(0.f,0.f,0.f,0.f); }
    pb = *(const float4*)&W[(size_t)lb_k*DH + lb_n];
    As[0][0][tid]=pa0.x; As[0][1][tid]=pa0.y; As[0][2][tid]=pa0.z; As[0][3][tid]=pa0.w;
    As[0][4][tid]=pa1.x; As[0][5][tid]=pa1.y; As[0][6][tid]=pa1.z; As[0][7][tid]=pa1.w;
    *(float4*)&Bs[0][lb_k][lb_n] = pb;
    __syncthreads();

    const int NC = KCH/8;  // 32 chunks
    for (int c = 0; c < NC; c++) {
        int cur = c & 1;
        if (c + 1 < NC) {
            int k0 = (c + 1) * 8;
            if (at >= 0) { pa0 = *(const float4*)(aptr + k0); pa1 = *(const float4*)(aptr + k0 + 4); }
            else { pa0 = pa1 = make_float4(0.f,0.f,0.f,0.f); }
            pb = *(const float4*)&W[(size_t)(k0 + lb_k)*DH + lb_n];
        }
#pragma unroll
        for (int kk = 0; kk < 8; kk++) {
            float4 a0 = *(const float4*)&As[cur][kk][tyy*8];
            float4 a1 = *(const float4*)&As[cur][kk][tyy*8+4];
            float4 b0 = *(const float4*)&Bs[cur][kk][txx*8];
            float4 b1 = *(const float4*)&Bs[cur][kk][txx*8+4];
            float av[8] = {a0.x,a0.y,a0.z,a0.w,a1.x,a1.y,a1.z,a1.w};
            float bv[8] = {b0.x,b0.y,b0.z,b0.w,b1.x,b1.y,b1.z,b1.w};
#pragma unroll
            for (int i = 0; i < 8; i++)
#pragma unroll
                for (int j = 0; j < 8; j++)
                    acc[i][j] += av[i] * bv[j];
        }
        if (c + 1 < NC) {
            int nxt = cur ^ 1;
            __syncthreads();
            As[nxt][0][tid]=pa0.x; As[nxt][1][tid]=pa0.y; As[nxt][2][tid]=pa0.z; As[nxt][3][tid]=pa0.w;
            As[nxt][4][tid]=pa1.x; As[nxt][5][tid]=pa1.y; As[nxt][6][tid]=pa1.z; As[nxt][7][tid]=pa1.w;
            *(float4*)&Bs[nxt][lb_k][lb_n] = pb;
            __syncthreads();
        }
    }
#pragma unroll
    for (int i = 0; i < 8; i++) {
        int m = tyy*8 + i;
        int t = ts[m];
        if (t < 0) continue;
        size_t base = ((size_t)(t>>11)*NH + h)*NSEQ + (t & 2047);
        *(float4*)&g_vpart[z][base*DH + txx*8] =
            make_float4(acc[i][0], acc[i][1], acc[i][2], acc[i][3]);
        *(float4*)&g_vpart[z][base*DH + txx*8 + 4] =
            make_float4(acc[i][4], acc[i][5], acc[i][6], acc[i][7]);
    }
}

// ---------------- kernel 3b: sum split-K partials, apply gate ----------------
__global__ void vreduce_kernel() {
    int idx = blockIdx.x * blockDim.x + threadIdx.x;
    const int total = BH*NSEQ*DH/4;
    if (idx >= total) return;
    int row = idx >> 4;              // DH/4 = 16 float4 per row
    float gate = g_gate[row];
    float4 s = make_float4(0.f,0.f,0.f,0.f);
#pragma unroll
    for (int zz = 0; zz < KSPLIT; zz++) {
        float4 v = ((const float4*)g_vpart[zz])[idx];
        s.x += v.x; s.y += v.y; s.z += v.z; s.w += v.w;
    }
    s.x *= gate; s.y *= gate; s.z *= gate; s.w *= gate;
    ((float4*)g_vals)[idx] = s;
}

// ---------------- kernel 4: causal flash attention (fp32) ----------------
#define QP 132
#define KP 68
#define ATTN_SMEM ((64*QP + 64*KP + 64*KP + 128*KP + 3*128) * 4)
__global__ void __launch_bounds__(256, 2)
attn_kernel() {
    extern __shared__ float sm[];
    float* Qs = sm;                  // [d][m] pitch QP
    float* Ks = Qs + 64*QP;          // [d][j] pitch KP
    float* Vs = Ks + 64*KP;          // [j][d] pitch KP
    float* Ps = Vs + 64*KP;          // [m][j] pitch KP
    float* m_s = Ps + 128*KP;
    float* l_s = m_s + 128;
    float* f_s = l_s + 128;
    int bh = blockIdx.x;
    int qt = (int)(gridDim.y - 1) - (int)blockIdx.y;  // heavy tiles first
    int qbase = qt * 128;
    int tid = threadIdx.x;
    int tyy = tid >> 4, txx = tid & 15;
    const float scale = 0.125f;

#pragma unroll
    for (int r = 0; r < 8; r++) {
        int id = tid + 256*r;
        int m = id >> 4, d4 = (id & 15) * 4;
        float4 v = *(const float4*)&g_q[((size_t)bh*NSEQ + qbase + m)*DH + d4];
        Qs[(d4+0)*QP + m] = v.x * scale;
        Qs[(d4+1)*QP + m] = v.y * scale;
        Qs[(d4+2)*QP + m] = v.z * scale;
        Qs[(d4+3)*QP + m] = v.w * scale;
    }
    if (tid < 128) { m_s[tid] = -1e30f; l_s[tid] = 0.f; }
    float o[8][4] = {};

    int ntiles = qt*2 + 2;
    for (int jt = 0; jt < ntiles; jt++) {
        __syncthreads();
#pragma unroll
        for (int r = 0; r < 4; r++) {
            int id = tid + 256*r;
            int j = id >> 4, d4 = (id & 15) * 4;
            float4 kv = *(const float4*)&g_k[((size_t)bh*NSEQ + jt*64 + j)*DH + d4];
            Ks[(d4+0)*KP + j] = kv.x;
            Ks[(d4+1)*KP + j] = kv.y;
            Ks[(d4+2)*KP + j] = kv.z;
            Ks[(d4+3)*KP + j] = kv.w;
            float4 vv = *(const float4*)&g_vals[((size_t)bh*NSEQ + jt*64 + j)*DH + d4];
            *(float4*)&Vs[j*KP + d4] = vv;
        }
        __syncthreads();
        float s[8][4] = {};
#pragma unroll 8
        for (int d = 0; d < 64; d++) {
            float4 a0 = *(const float4*)&Qs[d*QP + tyy*8];
            float4 a1 = *(const float4*)&Qs[d*QP + tyy*8 + 4];
            float4 b  = *(const float4*)&Ks[d*KP + txx*4];
            float av[8] = {a0.x,a0.y,a0.z,a0.w,a1.x,a1.y,a1.z,a1.w};
            float bv[4] = {b.x,b.y,b.z,b.w};
#pragma unroll
            for (int i = 0; i < 8; i++)
#pragma unroll
                for (int j = 0; j < 4; j++)
                    s[i][j] += av[i] * bv[j];
        }
        if (jt*64 + 63 > qbase + tyy*8) {
#pragma unroll
            for (int i = 0; i < 8; i++)
#pragma unroll
                for (int j = 0; j < 4; j++)
                    if (jt*64 + txx*4 + j > qbase + tyy*8 + i) s[i][j] = -1e30f;
        }
#pragma unroll
        for (int i = 0; i < 8; i++)
            *(float4*)&Ps[(tyy*8+i)*KP + txx*4] =
                make_float4(s[i][0], s[i][1], s[i][2], s[i][3]);
        __syncthreads();
        {
            int row = tid >> 1, half = tid & 1;
            float* P = &Ps[row*KP + half*32];
            float mx = m_s[row];
#pragma unroll 8
            for (int j2 = 0; j2 < 32; j2++) mx = fmaxf(mx, P[j2]);
            mx = fmaxf(mx, __shfl_xor_sync(0xffffffffu, mx, 1));
            float sum = 0.f;
#pragma unroll 8
            for (int j2 = 0; j2 < 32; j2++) {
                float p = __expf(P[j2] - mx); P[j2] = p; sum += p;
            }
            sum += __shfl_xor_sync(0xffffffffu, sum, 1);
            if (half == 0) {
                float mo = m_s[row];
                float f = __expf(mo - mx);
                m_s[row] = mx;
                l_s[row] = l_s[row]*f + sum;
                f_s[row] = f;
            }
        }
        __syncthreads();
        float fr[8];
#pragma unroll
        for (int i = 0; i < 8; i++) fr[i] = f_s[tyy*8 + i];
#pragma unroll
        for (int i = 0; i < 8; i++)
#pragma unroll
            for (int j = 0; j < 4; j++)
                o[i][j] *= fr[i];
#pragma unroll 8
        for (int jj = 0; jj < 64; jj++) {
            float4 b = *(const float4*)&Vs[jj*KP + txx*4];
            float bv[4] = {b.x,b.y,b.z,b.w};
#pragma unroll
            for (int i = 0; i < 8; i++) {
                float a = Ps[(tyy*8+i)*KP + jj];
#pragma unroll
                for (int j = 0; j < 4; j++)
                    o[i][j] += a * bv[j];
            }
        }
    }
#pragma unroll
    for (int i = 0; i < 8; i++) {
        int row = tyy*8 + i;
        float inv = 1.f / l_s[row];
        float4 ov = make_float4(o[i][0]*inv, o[i][1]*inv, o[i][2]*inv, o[i][3]*inv);
        *(float4*)&g_attn[((size_t)bh*NSEQ + qbase + row)*DH + txx*4] = ov;
    }
}

// ---------------- kernel 5: grouped output-expert GEMM ----------------
__global__ void __launch_bounds__(256, 2)
output_kernel(const float* __restrict__ oexp) {
    __shared__ float As[16][128];
    __shared__ float Bs[16][128];
    __shared__ int   ts[128];
    __shared__ float gts[128];
    int he = blockIdx.x; int h = he >> 3, e = he & 7;
    int cnt = g_cnt[he];
    int start = blockIdx.y * 128;
    if (start >= cnt) return;
    int ct = blockIdx.z;   // 0..7 (128-col tiles)
    int tid = threadIdx.x;
    if (tid < 128) {
        int t = (start + tid < cnt) ? g_list[(size_t)he*TTOK + start + tid] : -1;
        ts[tid] = t;
        gts[tid] = (t >= 0) ? g_gate[(size_t)((t>>11)*NH + h)*NSEQ + (t & 2047)] : 0.f;
    }
    __syncthreads();
    const float* W = oexp + (size_t)(e*NH + h)*DH*DIMM + ct*128;
    int tyy = tid >> 4, txx = tid & 15;
    float acc[8][8] = {};
    for (int k0 = 0; k0 < DH; k0 += 16) {
        if (k0) __syncthreads();
#pragma unroll
        for (int r = 0; r < 2; r++) {
            int id = tid + 256*r;
            int row = id >> 2, kq = (id & 3) * 4;
            int t = ts[row];
            float4 v = make_float4(0.f,0.f,0.f,0.f);
            if (t >= 0) {
                size_t base = ((size_t)(t>>11)*NH + h)*NSEQ + (t & 2047);
                v = *(const float4*)&g_attn[base*DH + k0 + kq];
                float g = gts[row];
                v.x *= g; v.y *= g; v.z *= g; v.w *= g;
            }
            As[kq+0][row] = v.x; As[kq+1][row] = v.y;
            As[kq+2][row] = v.z; As[kq+3][row] = v.w;
        }
#pragma unroll
        for (int r = 0; r < 2; r++) {
            int id = tid + 256*r;
            int k = id >> 5, n4 = (id & 31) * 4;
            *(float4*)&Bs[k][n4] = *(const float4*)&W[(size_t)(k0 + k)*DIMM + n4];
        }
        __syncthreads();
#pragma unroll
        for (int kk = 0; kk < 16; kk++) {
            float4 a0 = *(const float4*)&As[kk][tyy*8];
            float4 a1 = *(const float4*)&As[kk][tyy*8+4];
            float4 b0 = *(const float4*)&Bs[kk][txx*8];
            float4 b1 = *(const float4*)&Bs[kk][txx*8+4];
            float av[8] = {a0.x,a0.y,a0.z,a0.w,a1.x,a1.y,a1.z,a1.w};
            float bv[8] = {b0.x,b0.y,b0.z,b0.w,b1.x,b1.y,b1.z,b1.w};
#pragma unroll
            for (int i = 0; i < 8; i++)
#pragma unroll
                for (int j = 0; j < 8; j++)
                    acc[i][j] += av[i] * bv[j];
        }
    }
#pragma unroll
    for (int i = 0; i < 8; i++) {
        int m = tyy*8 + i;
        int t = ts[m];
        if (t < 0) continue;
        size_t base = ((size_t)(t>>11)*NH + h)*NSEQ + (t & 2047);
        float* dst = &g_outh[base*DIMM + ct*128 + txx*8];
        *(float4*)dst       = make_float4(acc[i][0], acc[i][1], acc[i][2], acc[i][3]);
        *(float4*)(dst + 4) = make_float4(acc[i][4], acc[i][5], acc[i][6], acc[i][7]);
    }
}

// ---------------- kernel 6: sum over heads ----------------
__global__ void reduce_kernel(float* __restrict__ out) {
    int idx = blockIdx.x * blockDim.x + threadIdx.x;
    const int total = TTOK * (DIMM/4);
    const float4* ph = (const float4*)g_outh;
    float4* po = (float4*)out;
    for (; idx < total; idx += gridDim.x * blockDim.x) {
        int t = idx >> 8;
        int d4 = idx & 255;
        int b_ = t >> 11, n = t & 2047;
        float4 s = make_float4(0.f,0.f,0.f,0.f);
#pragma unroll
        for (int h = 0; h < NH; h++) {
            float4 v = ph[((size_t)(b_*NH + h)*NSEQ + n)*256 + d4];
            s.x += v.x; s.y += v.y; s.z += v.z; s.w += v.w;
        }
        po[idx] = s;
    }
}

// ---------------- launch ----------------
extern "C" void kernel_launch(void* const* d_in, const int* in_sizes, int n_in,
                              void* d_out, int out_size) {
    const float* x  = (const float*)d_in[0];
    const float* wq = (const float*)d_in[1];
    const float* wk = (const float*)d_in[2];
    const float* wg = (const float*)d_in[3];
    const float* ve = (const float*)d_in[4];
    const float* oe = (const float*)d_in[5];
    float* out = (float*)d_out;

    cudaFuncSetAttribute(attn_kernel,
                         cudaFuncAttributeMaxDynamicSharedMemorySize, ATTN_SMEM);

    init_kernel<<<1, 64>>>();
    proj_kernel<<<dim3(32, 9), 256>>>(x, wq, wk, wg);
    gate_kernel<<<(TTOK*NH)/256, 256>>>();
    value_kernel<<<dim3(NH*NE, TTOK/128, KSPLIT), 128>>>(x, ve);
    vreduce_kernel<<<(BH*NSEQ*DH/4 + 255)/256, 256>>>();
    attn_kernel<<<dim3(BH, NSEQ/128), 256, ATTN_SMEM>>>();
    output_kernel<<<dim3(NH*NE, TTOK/128, DIMM/128), 256>>>(oe);
    reduce_kernel<<<2048, 256>>>(out);
}

// round 7
// speedup vs baseline: 1.1753x; 1.1753x over previous
#include <cuda_runtime.h>

#define BATCH 2
#define NSEQ  2048
#define DIMM  1024
#define NH    8
#define DH    64
#define NE    8
#define TTOK  (BATCH*NSEQ)     /* 4096 tokens */
#define BH    (BATCH*NH)       /* 16 */
#define GCOLS (NH*NE)          /* 64 gate columns */
#define KSPLIT 4
#define KCH   (DIMM/KSPLIT)    /* 256 */

typedef unsigned long long ull;

// packed fp32x2 FMA (SASS FFMA2) — ptxas never emits this from C++
__device__ __forceinline__ void ffma2(ull& d, ull a, ull b) {
    asm("fma.rn.f32x2 %0, %1, %2, %0;" : "+l"(d) : "l"(a), "l"(b));
}
__device__ __forceinline__ ull dup2(float a) {
    ull r; asm("mov.b64 %0, {%1, %1};" : "=l"(r) : "f"(a)); return r;
}
__device__ __forceinline__ void mul2(ull& d, ull a) {
    asm("mul.rn.f32x2 %0, %0, %1;" : "+l"(d) : "l"(a));
}
__device__ __forceinline__ float2 unpack2(ull v) {
    float2 f; asm("mov.b64 {%0, %1}, %2;" : "=f"(f.x), "=f"(f.y) : "l"(v)); return f;
}
union F4U2 { float4 f4; ull u2[2]; };

// ---------------- scratch (static device globals; allowed) ----------------
static __device__ float g_q[BH*NSEQ*DH];
static __device__ float g_k[BH*NSEQ*DH];
static __device__ float g_glogit[TTOK*GCOLS];
static __device__ float g_gate[BH*NSEQ];
static __device__ int   g_cnt[NH*NE];
static __device__ int   g_list[NH*NE*TTOK];
static __device__ float g_vpart[KSPLIT][BH*NSEQ*DH];   // split-K partials (32MB)
static __device__ float g_vals[BH*NSEQ*DH];
static __device__ float g_attn[BH*NSEQ*DH];
static __device__ float g_outh[(size_t)BH*NSEQ*DIMM];

__global__ void init_kernel() {
    int i = threadIdx.x;
    if (i < NH*NE) g_cnt[i] = 0;
}

// ---------------- kernel 1: fused QK+gate projection GEMM ----------------
// X(4096x1024) @ [Wq|Wk|Wgate](1024x1088). 128x128 tile, 256 thr, 8x8 micro,
// double-buffered K-chunks of 8, FFMA2 inner loop.
__global__ void __launch_bounds__(256, 2)
proj_kernel(const float* __restrict__ x,
            const float* __restrict__ wq,
            const float* __restrict__ wk,
            const float* __restrict__ wg) {
    __shared__ float As[2][8][128];   // [k][m]
    __shared__ float Bs[2][8][128];   // [k][n]
    int tid = threadIdx.x;
    int bm = blockIdx.x, bn = blockIdx.y;

    int la_row = tid >> 1;            // 0..127
    int la_k   = (tid & 1) * 4;       // 0 | 4
    const float* aptr = x + (size_t)(bm*128 + la_row)*DIMM + la_k;

    int lb_k = tid >> 5;              // 0..7
    int lb_n = (tid & 31) * 4;        // 0..124
    int gc   = bn*128 + lb_n;

    int tyy = tid >> 4, txx = tid & 15;
    ull acc2[8][4] = {};              // pairs of output cols
    float4 pa, pb;

    pa = *(const float4*)(aptr + 0);
    {
        int krow = lb_k;
        if (gc < 512)       pb = *(const float4*)&wq[(size_t)krow*512 + gc];
        else if (gc < 1024) pb = *(const float4*)&wk[(size_t)krow*512 + gc - 512];
        else if (gc < 1088) pb = *(const float4*)&wg[(size_t)krow*64  + gc - 1024];
        else                pb = make_float4(0.f,0.f,0.f,0.f);
    }
    As[0][la_k+0][la_row] = pa.x; As[0][la_k+1][la_row] = pa.y;
    As[0][la_k+2][la_row] = pa.z; As[0][la_k+3][la_row] = pa.w;
    *(float4*)&Bs[0][lb_k][lb_n] = pb;
    __syncthreads();

    const int NC = DIMM/8;
    for (int c = 0; c < NC; c++) {
        int cur = c & 1;
        if (c + 1 < NC) {
            int k0 = (c + 1) * 8;
            pa = *(const float4*)(aptr + k0);
            int krow = k0 + lb_k;
            if (gc < 512)       pb = *(const float4*)&wq[(size_t)krow*512 + gc];
            else if (gc < 1024) pb = *(const float4*)&wk[(size_t)krow*512 + gc - 512];
            else if (gc < 1088) pb = *(const float4*)&wg[(size_t)krow*64  + gc - 1024];
            else                pb = make_float4(0.f,0.f,0.f,0.f);
        }
#pragma unroll
        for (int kk = 0; kk < 8; kk++) {
            float4 a0 = *(const float4*)&As[cur][kk][tyy*8];
            float4 a1 = *(const float4*)&As[cur][kk][tyy*8+4];
            F4U2 B0, B1;
            B0.f4 = *(const float4*)&Bs[cur][kk][txx*8];
            B1.f4 = *(const float4*)&Bs[cur][kk][txx*8+4];
            float av[8] = {a0.x,a0.y,a0.z,a0.w,a1.x,a1.y,a1.z,a1.w};
#pragma unroll
            for (int i = 0; i < 8; i++) {
                ull aa = dup2(av[i]);
                ffma2(acc2[i][0], aa, B0.u2[0]);
                ffma2(acc2[i][1], aa, B0.u2[1]);
                ffma2(acc2[i][2], aa, B1.u2[0]);
                ffma2(acc2[i][3], aa, B1.u2[1]);
            }
        }
        if (c + 1 < NC) {
            int nxt = cur ^ 1;
            __syncthreads();
            As[nxt][la_k+0][la_row] = pa.x; As[nxt][la_k+1][la_row] = pa.y;
            As[nxt][la_k+2][la_row] = pa.z; As[nxt][la_k+3][la_row] = pa.w;
            *(float4*)&Bs[nxt][lb_k][lb_n] = pb;
            __syncthreads();
        }
    }
#pragma unroll
    for (int i = 0; i < 8; i++) {
        int row = bm*128 + tyy*8 + i;
        int b_ = row >> 11, n = row & 2047;
        float accf[8];
#pragma unroll
        for (int p = 0; p < 4; p++) {
            float2 f = unpack2(acc2[i][p]);
            accf[2*p] = f.x; accf[2*p+1] = f.y;
        }
#pragma unroll
        for (int j = 0; j < 8; j++) {
            int c = bn*128 + txx*8 + j;
            float v = accf[j];
            if (c < 512) {
                g_q[((size_t)(b_*NH + (c >> 6))*NSEQ + n)*DH + (c & 63)] = v;
            } else if (c < 1024) {
                int c2 = c - 512;
                g_k[((size_t)(b_*NH + (c2 >> 6))*NSEQ + n)*DH + (c2 & 63)] = v;
            } else if (c < 1088) {
                g_glogit[(size_t)row*GCOLS + (c - 1024)] = v;
            }
        }
    }
}

// ---------------- kernel 2: gate sigmoid + argmax + bucket append ----------------
__global__ void gate_kernel() {
    int id = blockIdx.x * blockDim.x + threadIdx.x;
    if (id >= TTOK*NH) return;
    int t = id / NH, h = id % NH;
    const float* lg = &g_glogit[(size_t)t*GCOLS + h*NE];
    float best = lg[0]; int be = 0;
#pragma unroll
    for (int e = 1; e < NE; e++) { float v = lg[e]; if (v > best) { best = v; be = e; } }
    float gate = 1.f / (1.f + __expf(-best));
    int b_ = t >> 11, n = t & 2047;
    g_gate[(size_t)(b_*NH + h)*NSEQ + n] = gate;
    int pos = atomicAdd(&g_cnt[h*NE + be], 1);
    g_list[(size_t)(h*NE + be)*TTOK + pos] = t;
}

// ---------------- kernel 3: grouped value-expert GEMM, split-K x4 ----------------
__global__ void __launch_bounds__(128, 4)
value_kernel(const float* __restrict__ x,
             const float* __restrict__ vexp) {
    __shared__ float As[2][8][128];
    __shared__ float Bs[2][8][64];
    __shared__ int   ts[128];
    int he = blockIdx.x; int h = he >> 3, e = he & 7;
    int cnt = g_cnt[he];
    int start = blockIdx.y * 128;
    if (start >= cnt) return;
    int z = blockIdx.z;
    int kbase = z * KCH;
    int tid = threadIdx.x;
    ts[tid] = (start + tid < cnt) ? g_list[(size_t)he*TTOK + start + tid] : -1;
    __syncthreads();
    const float* W = vexp + (size_t)(e*NH + h)*DIMM*DH + (size_t)kbase*DH;
    int at = ts[tid];
    const float* aptr = x + (size_t)(at >= 0 ? at : 0)*DIMM + kbase;
    int lb_k = tid >> 4, lb_n = (tid & 15) * 4;
    int tyy = tid >> 3, txx = tid & 7;
    ull acc2[8][4] = {};
    float4 pa0, pa1, pb;

    if (at >= 0) { pa0 = *(const float4*)(aptr + 0); pa1 = *(const float4*)(aptr + 4); }
    else { pa0 = pa1 = make_float4(0.f,0.f,0.f,0.f); }
    pb = *(const float4*)&W[(size_t)lb_k*DH + lb_n];
    As[0][0][tid]=pa0.x; As[0][1][tid]=pa0.y; As[0][2][tid]=pa0.z; As[0][3][tid]=pa0.w;
    As[0][4][tid]=pa1.x; As[0][5][tid]=pa1.y; As[0][6][tid]=pa1.z; As[0][7][tid]=pa1.w;
    *(float4*)&Bs[0][lb_k][lb_n] = pb;
    __syncthreads();

    const int NC = KCH/8;  // 32 chunks
    for (int c = 0; c < NC; c++) {
        int cur = c & 1;
        if (c + 1 < NC) {
            int k0 = (c + 1) * 8;
            if (at >= 0) { pa0 = *(const float4*)(aptr + k0); pa1 = *(const float4*)(aptr + k0 + 4); }
            else { pa0 = pa1 = make_float4(0.f,0.f,0.f,0.f); }
            pb = *(const float4*)&W[(size_t)(k0 + lb_k)*DH + lb_n];
        }
#pragma unroll
        for (int kk = 0; kk < 8; kk++) {
            float4 a0 = *(const float4*)&As[cur][kk][tyy*8];
            float4 a1 = *(const float4*)&As[cur][kk][tyy*8+4];
            F4U2 B0, B1;
            B0.f4 = *(const float4*)&Bs[cur][kk][txx*8];
            B1.f4 = *(const float4*)&Bs[cur][kk][txx*8+4];
            float av[8] = {a0.x,a0.y,a0.z,a0.w,a1.x,a1.y,a1.z,a1.w};
#pragma unroll
            for (int i = 0; i < 8; i++) {
                ull aa = dup2(av[i]);
                ffma2(acc2[i][0], aa, B0.u2[0]);
                ffma2(acc2[i][1], aa, B0.u2[1]);
                ffma2(acc2[i][2], aa, B1.u2[0]);
                ffma2(acc2[i][3], aa, B1.u2[1]);
            }
        }
        if (c + 1 < NC) {
            int nxt = cur ^ 1;
            __syncthreads();
            As[nxt][0][tid]=pa0.x; As[nxt][1][tid]=pa0.y; As[nxt][2][tid]=pa0.z; As[nxt][3][tid]=pa0.w;
            As[nxt][4][tid]=pa1.x; As[nxt][5][tid]=pa1.y; As[nxt][6][tid]=pa1.z; As[nxt][7][tid]=pa1.w;
            *(float4*)&Bs[nxt][lb_k][lb_n] = pb;
            __syncthreads();
        }
    }
#pragma unroll
    for (int i = 0; i < 8; i++) {
        int m = tyy*8 + i;
        int t = ts[m];
        if (t < 0) continue;
        size_t base = ((size_t)(t>>11)*NH + h)*NSEQ + (t & 2047);
        float2 f0 = unpack2(acc2[i][0]), f1 = unpack2(acc2[i][1]);
        float2 f2 = unpack2(acc2[i][2]), f3 = unpack2(acc2[i][3]);
        *(float4*)&g_vpart[z][base*DH + txx*8]     = make_float4(f0.x, f0.y, f1.x, f1.y);
        *(float4*)&g_vpart[z][base*DH + txx*8 + 4] = make_float4(f2.x, f2.y, f3.x, f3.y);
    }
}

// ---------------- kernel 3b: sum split-K partials, apply gate ----------------
__global__ void vreduce_kernel() {
    int idx = blockIdx.x * blockDim.x + threadIdx.x;
    const int total = BH*NSEQ*DH/4;
    if (idx >= total) return;
    int row = idx >> 4;
    float gate = g_gate[row];
    float4 s = make_float4(0.f,0.f,0.f,0.f);
#pragma unroll
    for (int zz = 0; zz < KSPLIT; zz++) {
        float4 v = ((const float4*)g_vpart[zz])[idx];
        s.x += v.x; s.y += v.y; s.z += v.z; s.w += v.w;
    }
    s.x *= gate; s.y *= gate; s.z *= gate; s.w *= gate;
    ((float4*)g_vals)[idx] = s;
}

// ---------------- kernel 4: causal flash attention (fp32, FFMA2) ----------------
#define QP 132
#define KP 68
#define ATTN_SMEM ((64*QP + 64*KP + 64*KP + 128*KP + 3*128) * 4)
__global__ void __launch_bounds__(256, 1)
attn_kernel() {
    extern __shared__ float sm[];
    float* Qs = sm;                  // [d][m] pitch QP
    float* Ks = Qs + 64*QP;          // [d][j] pitch KP
    float* Vs = Ks + 64*KP;          // [j][d] pitch KP
    float* Ps = Vs + 64*KP;          // [m][j] pitch KP
    float* m_s = Ps + 128*KP;
    float* l_s = m_s + 128;
    float* f_s = l_s + 128;
    int bh = blockIdx.x;
    int qt = (int)(gridDim.y - 1) - (int)blockIdx.y;  // heavy tiles first
    int qbase = qt * 128;
    int tid = threadIdx.x;
    int tyy = tid >> 4, txx = tid & 15;
    const float scale = 0.125f;

#pragma unroll
    for (int r = 0; r < 8; r++) {
        int id = tid + 256*r;
        int m = id >> 4, d4 = (id & 15) * 4;
        float4 v = *(const float4*)&g_q[((size_t)bh*NSEQ + qbase + m)*DH + d4];
        Qs[(d4+0)*QP + m] = v.x * scale;
        Qs[(d4+1)*QP + m] = v.y * scale;
        Qs[(d4+2)*QP + m] = v.z * scale;
        Qs[(d4+3)*QP + m] = v.w * scale;
    }
    if (tid < 128) { m_s[tid] = -1e30f; l_s[tid] = 0.f; }
    ull o2[8][2] = {};

    int ntiles = qt*2 + 2;
    for (int jt = 0; jt < ntiles; jt++) {
        __syncthreads();
#pragma unroll
        for (int r = 0; r < 4; r++) {
            int id = tid + 256*r;
            int j = id >> 4, d4 = (id & 15) * 4;
            float4 kv = *(const float4*)&g_k[((size_t)bh*NSEQ + jt*64 + j)*DH + d4];
            Ks[(d4+0)*KP + j] = kv.x;
            Ks[(d4+1)*KP + j] = kv.y;
            Ks[(d4+2)*KP + j] = kv.z;
            Ks[(d4+3)*KP + j] = kv.w;
            float4 vv = *(const float4*)&g_vals[((size_t)bh*NSEQ + jt*64 + j)*DH + d4];
            *(float4*)&Vs[j*KP + d4] = vv;
        }
        __syncthreads();
        ull s2[8][2] = {};
#pragma unroll 8
        for (int d = 0; d < 64; d++) {
            float4 a0 = *(const float4*)&Qs[d*QP + tyy*8];
            float4 a1 = *(const float4*)&Qs[d*QP + tyy*8 + 4];
            F4U2 B; B.f4 = *(const float4*)&Ks[d*KP + txx*4];
            float av[8] = {a0.x,a0.y,a0.z,a0.w,a1.x,a1.y,a1.z,a1.w};
#pragma unroll
            for (int i = 0; i < 8; i++) {
                ull aa = dup2(av[i]);
                ffma2(s2[i][0], aa, B.u2[0]);
                ffma2(s2[i][1], aa, B.u2[1]);
            }
        }
        float s[8][4];
#pragma unroll
        for (int i = 0; i < 8; i++) {
            float2 f0 = unpack2(s2[i][0]), f1 = unpack2(s2[i][1]);
            s[i][0] = f0.x; s[i][1] = f0.y; s[i][2] = f1.x; s[i][3] = f1.y;
        }
        if (jt*64 + 63 > qbase + tyy*8) {
#pragma unroll
            for (int i = 0; i < 8; i++)
#pragma unroll
                for (int j = 0; j < 4; j++)
                    if (jt*64 + txx*4 + j > qbase + tyy*8 + i) s[i][j] = -1e30f;
        }
#pragma unroll
        for (int i = 0; i < 8; i++)
            *(float4*)&Ps[(tyy*8+i)*KP + txx*4] =
                make_float4(s[i][0], s[i][1], s[i][2], s[i][3]);
        __syncthreads();
        {
            int row = tid >> 1, half = tid & 1;
            float* P = &Ps[row*KP + half*32];
            float mx = m_s[row];
#pragma unroll 8
            for (int j2 = 0; j2 < 32; j2++) mx = fmaxf(mx, P[j2]);
            mx = fmaxf(mx, __shfl_xor_sync(0xffffffffu, mx, 1));
            float sum = 0.f;
#pragma unroll 8
            for (int j2 = 0; j2 < 32; j2++) {
                float p = __expf(P[j2] - mx); P[j2] = p; sum += p;
            }
            sum += __shfl_xor_sync(0xffffffffu, sum, 1);
            if (half == 0) {
                float mo = m_s[row];
                float f = __expf(mo - mx);
                m_s[row] = mx;
                l_s[row] = l_s[row]*f + sum;
                f_s[row] = f;
            }
        }
        __syncthreads();
#pragma unroll
        for (int i = 0; i < 8; i++) {
            ull ff = dup2(f_s[tyy*8 + i]);
            mul2(o2[i][0], ff);
            mul2(o2[i][1], ff);
        }
#pragma unroll 8
        for (int jj = 0; jj < 64; jj++) {
            F4U2 B; B.f4 = *(const float4*)&Vs[jj*KP + txx*4];
#pragma unroll
            for (int i = 0; i < 8; i++) {
                ull aa = dup2(Ps[(tyy*8+i)*KP + jj]);
                ffma2(o2[i][0], aa, B.u2[0]);
                ffma2(o2[i][1], aa, B.u2[1]);
            }
        }
    }
#pragma unroll
    for (int i = 0; i < 8; i++) {
        int row = tyy*8 + i;
        float inv = 1.f / l_s[row];
        float2 f0 = unpack2(o2[i][0]), f1 = unpack2(o2[i][1]);
        float4 ov = make_float4(f0.x*inv, f0.y*inv, f1.x*inv, f1.y*inv);
        *(float4*)&g_attn[((size_t)bh*NSEQ + qbase + row)*DH + txx*4] = ov;
    }
}

// ---------------- kernel 5: grouped output-expert GEMM ----------------
__global__ void __launch_bounds__(256, 2)
output_kernel(const float* __restrict__ oexp) {
    __shared__ float As[16][128];
    __shared__ float Bs[16][128];
    __shared__ int   ts[128];
    __shared__ float gts[128];
    int he = blockIdx.x; int h = he >> 3, e = he & 7;
    int cnt = g_cnt[he];
    int start = blockIdx.y * 128;
    if (start >= cnt) return;
    int ct = blockIdx.z;   // 0..7 (128-col tiles)
    int tid = threadIdx.x;
    if (tid < 128) {
        int t = (start + tid < cnt) ? g_list[(size_t)he*TTOK + start + tid] : -1;
        ts[tid] = t;
        gts[tid] = (t >= 0) ? g_gate[(size_t)((t>>11)*NH + h)*NSEQ + (t & 2047)] : 0.f;
    }
    __syncthreads();
    const float* W = oexp + (size_t)(e*NH + h)*DH*DIMM + ct*128;
    int tyy = tid >> 4, txx = tid & 15;
    ull acc2[8][4] = {};
    for (int k0 = 0; k0 < DH; k0 += 16) {
        if (k0) __syncthreads();
#pragma unroll
        for (int r = 0; r < 2; r++) {
            int id = tid + 256*r;
            int row = id >> 2, kq = (id & 3) * 4;
            int t = ts[row];
            float4 v = make_float4(0.f,0.f,0.f,0.f);
            if (t >= 0) {
                size_t base = ((size_t)(t>>11)*NH + h)*NSEQ + (t & 2047);
                v = *(const float4*)&g_attn[base*DH + k0 + kq];
                float g = gts[row];
                v.x *= g; v.y *= g; v.z *= g; v.w *= g;
            }
            As[kq+0][row] = v.x; As[kq+1][row] = v.y;
            As[kq+2][row] = v.z; As[kq+3][row] = v.w;
        }
#pragma unroll
        for (int r = 0; r < 2; r++) {
            int id = tid + 256*r;
            int k = id >> 5, n4 = (id & 31) * 4;
            *(float4*)&Bs[k][n4] = *(const float4*)&W[(size_t)(k0 + k)*DIMM + n4];
        }
        __syncthreads();
#pragma unroll
        for (int kk = 0; kk < 16; kk++) {
            float4 a0 = *(const float4*)&As[kk][tyy*8];
            float4 a1 = *(const float4*)&As[kk][tyy*8+4];
            F4U2 B0, B1;
            B0.f4 = *(const float4*)&Bs[kk][txx*8];
            B1.f4 = *(const float4*)&Bs[kk][txx*8+4];
            float av[8] = {a0.x,a0.y,a0.z,a0.w,a1.x,a1.y,a1.z,a1.w};
#pragma unroll
            for (int i = 0; i < 8; i++) {
                ull aa = dup2(av[i]);
                ffma2(acc2[i][0], aa, B0.u2[0]);
                ffma2(acc2[i][1], aa, B0.u2[1]);
                ffma2(acc2[i][2], aa, B1.u2[0]);
                ffma2(acc2[i][3], aa, B1.u2[1]);
            }
        }
    }
#pragma unroll
    for (int i = 0; i < 8; i++) {
        int m = tyy*8 + i;
        int t = ts[m];
        if (t < 0) continue;
        size_t base = ((size_t)(t>>11)*NH + h)*NSEQ + (t & 2047);
        float* dst = &g_outh[base*DIMM + ct*128 + txx*8];
        float2 f0 = unpack2(acc2[i][0]), f1 = unpack2(acc2[i][1]);
        float2 f2 = unpack2(acc2[i][2]), f3 = unpack2(acc2[i][3]);
        *(float4*)dst       = make_float4(f0.x, f0.y, f1.x, f1.y);
        *(float4*)(dst + 4) = make_float4(f2.x, f2.y, f3.x, f3.y);
    }
}

// ---------------- kernel 6: sum over heads ----------------
__global__ void reduce_kernel(float* __restrict__ out) {
    int idx = blockIdx.x * blockDim.x + threadIdx.x;
    const int total = TTOK * (DIMM/4);
    const float4* ph = (const float4*)g_outh;
    float4* po = (float4*)out;
    for (; idx < total; idx += gridDim.x * blockDim.x) {
        int t = idx >> 8;
        int d4 = idx & 255;
        int b_ = t >> 11, n = t & 2047;
        float4 s = make_float4(0.f,0.f,0.f,0.f);
#pragma unroll
        for (int h = 0; h < NH; h++) {
            float4 v = ph[((size_t)(b_*NH + h)*NSEQ + n)*256 + d4];
            s.x += v.x; s.y += v.y; s.z += v.z; s.w += v.w;
        }
        po[idx] = s;
    }
}

// ---------------- launch ----------------
extern "C" void kernel_launch(void* const* d_in, const int* in_sizes, int n_in,
                              void* d_out, int out_size) {
    const float* x  = (const float*)d_in[0];
    const float* wq = (const float*)d_in[1];
    const float* wk = (const float*)d_in[2];
    const float* wg = (const float*)d_in[3];
    const float* ve = (const float*)d_in[4];
    const float* oe = (const float*)d_in[5];
    float* out = (float*)d_out;

    cudaFuncSetAttribute(attn_kernel,
                         cudaFuncAttributeMaxDynamicSharedMemorySize, ATTN_SMEM);

    init_kernel<<<1, 64>>>();
    proj_kernel<<<dim3(32, 9), 256>>>(x, wq, wk, wg);
    gate_kernel<<<(TTOK*NH)/256, 256>>>();
    value_kernel<<<dim3(NH*NE, TTOK/128, KSPLIT), 128>>>(x, ve);
    vreduce_kernel<<<(BH*NSEQ*DH/4 + 255)/256, 256>>>();
    attn_kernel<<<dim3(BH, NSEQ/128), 256, ATTN_SMEM>>>();
    output_kernel<<<dim3(NH*NE, TTOK/128, DIMM/128), 256>>>(oe);
    reduce_kernel<<<2048, 256>>>(out);
}

// round 10
// speedup vs baseline: 1.6414x; 1.3965x over previous
#include <cuda_runtime.h>
#include <cuda_bf16.h>

#define BATCH 2
#define NSEQ  2048
#define DIMM  1024
#define NH    8
#define DH    64
#define NE    8
#define TTOK  (BATCH*NSEQ)     /* 4096 */
#define BH    (BATCH*NH)       /* 16 */
#define GCOLS (NH*NE)          /* 64 */

typedef unsigned long long ull;

// ---------------- packed fp32x2 helpers (attn) ----------------
__device__ __forceinline__ void ffma2(ull& d, ull a, ull b) {
    asm("fma.rn.f32x2 %0, %1, %2, %0;" : "+l"(d) : "l"(a), "l"(b));
}
__device__ __forceinline__ ull dup2(float a) {
    ull r; asm("mov.b64 %0, {%1, %1};" : "=l"(r) : "f"(a)); return r;
}
__device__ __forceinline__ void mul2(ull& d, ull a) {
    asm("mul.rn.f32x2 %0, %0, %1;" : "+l"(d) : "l"(a));
}
__device__ __forceinline__ float2 unpack2(ull v) {
    float2 f; asm("mov.b64 {%0, %1}, %2;" : "=f"(f.x), "=f"(f.y) : "l"(v)); return f;
}
union F4U2 { float4 f4; ull u2[2]; };

// ---------------- warp-MMA helpers (sm_80+ PTX, works on sm_100 base) ----------------
__device__ __forceinline__ unsigned smem_u32(const void* p) {
    unsigned a;
    asm("{ .reg .u64 t; cvta.to.shared.u64 t, %1; cvt.u32.u64 %0, t; }" : "=r"(a) : "l"(p));
    return a;
}
__device__ __forceinline__ void ldsm_x4(unsigned& r0, unsigned& r1, unsigned& r2, unsigned& r3,
                                        unsigned addr) {
    asm volatile("ldmatrix.sync.aligned.m8n8.x4.shared.b16 {%0,%1,%2,%3}, [%4];"
                 : "=r"(r0), "=r"(r1), "=r"(r2), "=r"(r3) : "r"(addr));
}
__device__ __forceinline__ void ldsm_x2t(unsigned& r0, unsigned& r1, unsigned addr) {
    asm volatile("ldmatrix.sync.aligned.m8n8.x2.trans.shared.b16 {%0,%1}, [%2];"
                 : "=r"(r0), "=r"(r1) : "r"(addr));
}
__device__ __forceinline__ void mma_bf16(float* c,
                                         unsigned a0, unsigned a1, unsigned a2, unsigned a3,
                                         unsigned b0, unsigned b1) {
    asm volatile("mma.sync.aligned.m16n8k16.row.col.f32.bf16.bf16.f32 "
                 "{%0,%1,%2,%3}, {%4,%5,%6,%7}, {%8,%9}, {%0,%1,%2,%3};"
                 : "+f"(c[0]), "+f"(c[1]), "+f"(c[2]), "+f"(c[3])
                 : "r"(a0), "r"(a1), "r"(a2), "r"(a3), "r"(b0), "r"(b1));
}

// split fp32x8 into hi/lo bf16x8, store 16B each to smem (byte offsets)
__device__ __forceinline__ void split_store8(char* hi_base, char* lo_base, unsigned off,
                                             float4 v0, float4 v1) {
    float v[8] = {v0.x, v0.y, v0.z, v0.w, v1.x, v1.y, v1.z, v1.w};
    unsigned hw[4], lw[4];
#pragma unroll
    for (int p = 0; p < 4; p++) {
        __nv_bfloat16 b0 = __float2bfloat16_rn(v[2*p]);
        __nv_bfloat16 b1 = __float2bfloat16_rn(v[2*p+1]);
        __nv_bfloat162 hh = __halves2bfloat162(b0, b1);
        hw[p] = *(unsigned*)&hh;
        float l0 = v[2*p]   - __bfloat162float(b0);
        float l1 = v[2*p+1] - __bfloat162float(b1);
        __nv_bfloat162 ll = __floats2bfloat162_rn(l0, l1);
        lw[p] = *(unsigned*)&ll;
    }
    *(uint4*)(hi_base + off) = make_uint4(hw[0], hw[1], hw[2], hw[3]);
    *(uint4*)(lo_base + off) = make_uint4(lw[0], lw[1], lw[2], lw[3]);
}

// ---------------- scratch ----------------
static __device__ float g_q[BH*NSEQ*DH];
static __device__ float g_k[BH*NSEQ*DH];
static __device__ float g_gpart[8][TTOK*GCOLS];
static __device__ float g_gate[BH*NSEQ];
static __device__ int   g_cnt[NH*NE];
static __device__ int   g_list[NH*NE*TTOK];
static __device__ float g_vals[BH*NSEQ*DH];
static __device__ float g_attn[BH*NSEQ*DH];
static __device__ float g_outh[(size_t)BH*NSEQ*DIMM];

__global__ void init_kernel() {
    int i = threadIdx.x;
    if (i < NH*NE) g_cnt[i] = 0;
}

// ---------------- smem layout for MMA kernels (bytes) ----------------
// rows padded to 72 bf16 (144B = 36 words; 36 mod 32 = 4 -> ldmatrix conflict-free)
#define LDA   72
#define SM_TS   0
#define SM_GTS  512
#define SM_AHI  1024
#define SM_ALO  (SM_AHI + 128*LDA*2)      /* +18432 */
#define SM_BHI  (SM_ALO + 128*LDA*2)
#define SM_BLO  (SM_BHI + 64*LDA*2)       /* +9216 */
#define TENS_SMEM (SM_BLO + 64*LDA*2)     /* 56320 */

// warp compute over one 64-K chunk: 4 ksteps x (2m x 4n) x 3 split terms
__device__ __forceinline__ void mma_chunk(float c[2][4][4], unsigned sb,
                                          int wm, int wn, int lane) {
#pragma unroll
    for (int ks = 0; ks < 4; ks++) {
        int k0 = ks * 16;
        unsigned ah[2][4], al[2][4], bh[4][2], bl[4][2];
#pragma unroll
        for (int mt = 0; mt < 2; mt++) {
            int row = wm*32 + mt*16 + (lane & 15);
            unsigned off = (unsigned)(row*LDA + k0 + (lane >> 4)*8) * 2;
            ldsm_x4(ah[mt][0], ah[mt][1], ah[mt][2], ah[mt][3], sb + SM_AHI + off);
            ldsm_x4(al[mt][0], al[mt][1], al[mt][2], al[mt][3], sb + SM_ALO + off);
        }
#pragma unroll
        for (int nt = 0; nt < 4; nt++) {
            int n0 = wn*32 + nt*8;
            unsigned off = (unsigned)((k0 + (lane & 15))*LDA + n0) * 2;
            ldsm_x2t(bh[nt][0], bh[nt][1], sb + SM_BHI + off);
            ldsm_x2t(bl[nt][0], bl[nt][1], sb + SM_BLO + off);
        }
#pragma unroll
        for (int mt = 0; mt < 2; mt++)
#pragma unroll
            for (int nt = 0; nt < 4; nt++) {
                mma_bf16(c[mt][nt], ah[mt][0], ah[mt][1], ah[mt][2], ah[mt][3],
                         bh[nt][0], bh[nt][1]);
                mma_bf16(c[mt][nt], ah[mt][0], ah[mt][1], ah[mt][2], ah[mt][3],
                         bl[nt][0], bl[nt][1]);
                mma_bf16(c[mt][nt], al[mt][0], al[mt][1], al[mt][2], al[mt][3],
                         bh[nt][0], bh[nt][1]);
            }
    }
}

// ---------------- kernel 1: proj Q/K via warp MMA (bf16 3-term split) ----------------
__global__ void __launch_bounds__(256, 2)
projt_kernel(const float* __restrict__ x,
             const float* __restrict__ wq,
             const float* __restrict__ wk) {
    extern __shared__ __align__(128) char smem[];
    unsigned sb = smem_u32(smem);
    int tid = threadIdx.x, wid = tid >> 5, lane = tid & 31;
    int bm = blockIdx.x, bn = blockIdx.y;           // bn: 16 tiles of 64 cols over Q|K
    int wm = wid & 3, wn = wid >> 2;
    const float* W = (bn < 8) ? wq : wk;
    int colbase = (bn & 7) * 64;

    float c[2][4][4] = {};
    for (int ch = 0; ch < 16; ch++) {
        if (ch) __syncthreads();
        // A: 128 tok x 64 k
#pragma unroll
        for (int r = 0; r < 4; r++) {
            int task = tid + 256*r;
            int row = task >> 3, kg = task & 7;
            const float* p = x + (size_t)(bm*128 + row)*DIMM + ch*64 + kg*8;
            split_store8(smem + SM_AHI, smem + SM_ALO,
                         (unsigned)(row*LDA + kg*8)*2,
                         *(const float4*)p, *(const float4*)(p + 4));
        }
        // B: 64 k x 64 n ([K][N] gmem, same layout in smem; trans-ldmatrix later)
#pragma unroll
        for (int r = 0; r < 2; r++) {
            int task = tid + 256*r;
            int krow = task >> 3, ng = task & 7;
            const float* p = W + (size_t)(ch*64 + krow)*512 + colbase + ng*8;
            split_store8(smem + SM_BHI, smem + SM_BLO,
                         (unsigned)(krow*LDA + ng*8)*2,
                         *(const float4*)p, *(const float4*)(p + 4));
        }
        __syncthreads();
        mma_chunk(c, sb, wm, wn, lane);
    }
    // epilogue
#pragma unroll
    for (int mt = 0; mt < 2; mt++)
#pragma unroll
        for (int nt = 0; nt < 4; nt++) {
            int r0 = bm*128 + wm*32 + mt*16 + (lane >> 2);
            int col = bn*64 + wn*32 + nt*8 + (lane & 3)*2;
            int b0_ = r0 >> 11, n0_ = r0 & 2047;
            int b1_ = (r0+8) >> 11, n1_ = (r0+8) & 2047;
            float* d0;
            float* d1;
            if (col < 512) {
                d0 = &g_q[((size_t)(b0_*NH + (col >> 6))*NSEQ + n0_)*DH + (col & 63)];
                d1 = &g_q[((size_t)(b1_*NH + (col >> 6))*NSEQ + n1_)*DH + (col & 63)];
            } else {
                int c2 = col - 512;
                d0 = &g_k[((size_t)(b0_*NH + (c2 >> 6))*NSEQ + n0_)*DH + (c2 & 63)];
                d1 = &g_k[((size_t)(b1_*NH + (c2 >> 6))*NSEQ + n1_)*DH + (c2 & 63)];
            }
            *(float2*)d0 = make_float2(c[mt][nt][0], c[mt][nt][1]);
            *(float2*)d1 = make_float2(c[mt][nt][2], c[mt][nt][3]);
        }
}

// ---------------- kernel 2: fp32 gate logits (split-K, exact routing) ----------------
__global__ void glogit_kernel(const float* __restrict__ x, const float* __restrict__ wg) {
    __shared__ float As[16][132];
    __shared__ float Bs[16][68];
    int tid = threadIdx.x;
    int bm = blockIdx.x, kz = blockIdx.y;
    int ty = tid >> 4, tx = tid & 15;
    float acc[8][4] = {};
    for (int kc = 0; kc < 8; kc++) {
#pragma unroll
        for (int r = 0; r < 8; r++) {
            int idx = tid + 256*r;
            int tok = idx >> 4, k = idx & 15;
            As[k][tok] = x[(size_t)(bm*128 + tok)*DIMM + kz*128 + kc*16 + k];
        }
#pragma unroll
        for (int r = 0; r < 4; r++) {
            int idx = tid + 256*r;
            int k = idx >> 6, c2 = idx & 63;
            Bs[k][c2] = wg[(size_t)(kz*128 + kc*16 + k)*GCOLS + c2];
        }
        __syncthreads();
#pragma unroll
        for (int k = 0; k < 16; k++) {
            float a_[8], b_[4];
#pragma unroll
            for (int i = 0; i < 8; i++) a_[i] = As[k][ty*8 + i];
#pragma unroll
            for (int j = 0; j < 4; j++) b_[j] = Bs[k][tx*4 + j];
#pragma unroll
            for (int i = 0; i < 8; i++)
#pragma unroll
                for (int j = 0; j < 4; j++)
                    acc[i][j] += a_[i] * b_[j];
        }
        __syncthreads();
    }
#pragma unroll
    for (int i = 0; i < 8; i++)
#pragma unroll
        for (int j = 0; j < 4; j++)
            g_gpart[kz][(size_t)(bm*128 + ty*8 + i)*GCOLS + tx*4 + j] = acc[i][j];
}

// ---------------- kernel 3: gate sigmoid + argmax + bucket append ----------------
__global__ void gate_kernel() {
    int id = blockIdx.x * blockDim.x + threadIdx.x;
    if (id >= TTOK*NH) return;
    int t = id / NH, h = id % NH;
    float lg[NE] = {};
#pragma unroll
    for (int kz = 0; kz < 8; kz++) {
        const float* gp = &g_gpart[kz][(size_t)t*GCOLS + h*NE];
        float4 a = *(const float4*)gp, b = *(const float4*)(gp + 4);
        lg[0]+=a.x; lg[1]+=a.y; lg[2]+=a.z; lg[3]+=a.w;
        lg[4]+=b.x; lg[5]+=b.y; lg[6]+=b.z; lg[7]+=b.w;
    }
    float best = lg[0]; int be = 0;
#pragma unroll
    for (int e = 1; e < NE; e++) { if (lg[e] > best) { best = lg[e]; be = e; } }
    float gate = 1.f / (1.f + __expf(-best));
    int b_ = t >> 11, n = t & 2047;
    g_gate[(size_t)(b_*NH + h)*NSEQ + n] = gate;
    int pos = atomicAdd(&g_cnt[h*NE + be], 1);
    g_list[(size_t)(h*NE + be)*TTOK + pos] = t;
}

// ---------------- kernel 4: value-expert GEMM via warp MMA ----------------
__global__ void __launch_bounds__(256, 2)
valt_kernel(const float* __restrict__ x, const float* __restrict__ vexp) {
    extern __shared__ __align__(128) char smem[];
    int he = blockIdx.x; int h = he >> 3, e = he & 7;
    int cnt = g_cnt[he];
    int start = blockIdx.y * 128;
    if (start >= cnt) return;
    unsigned sb = smem_u32(smem);
    int tid = threadIdx.x, wid = tid >> 5, lane = tid & 31;
    int wm = wid & 3, wn = wid >> 2;
    int* ts = (int*)(smem + SM_TS);
    float* gts = (float*)(smem + SM_GTS);
    if (tid < 128) {
        int t = (start + tid < cnt) ? g_list[(size_t)he*TTOK + start + tid] : -1;
        ts[tid] = t;
        gts[tid] = (t >= 0) ? g_gate[(size_t)((t>>11)*NH + h)*NSEQ + (t & 2047)] : 0.f;
    }
    __syncthreads();
    const float* B = vexp + (size_t)(e*NH + h)*DIMM*DH;

    float c[2][4][4] = {};
    for (int ch = 0; ch < 16; ch++) {
        if (ch) __syncthreads();
#pragma unroll
        for (int r = 0; r < 4; r++) {
            int task = tid + 256*r;
            int row = task >> 3, kg = task & 7;
            int t = ts[row];
            float4 v0 = make_float4(0.f,0.f,0.f,0.f), v1 = v0;
            if (t >= 0) {
                const float* p = x + (size_t)t*DIMM + ch*64 + kg*8;
                v0 = *(const float4*)p; v1 = *(const float4*)(p + 4);
                float g = gts[row];
                v0.x*=g; v0.y*=g; v0.z*=g; v0.w*=g;
                v1.x*=g; v1.y*=g; v1.z*=g; v1.w*=g;
            }
            split_store8(smem + SM_AHI, smem + SM_ALO,
                         (unsigned)(row*LDA + kg*8)*2, v0, v1);
        }
#pragma unroll
        for (int r = 0; r < 2; r++) {
            int task = tid + 256*r;
            int krow = task >> 3, ng = task & 7;
            const float* p = B + (size_t)(ch*64 + krow)*DH + ng*8;
            split_store8(smem + SM_BHI, smem + SM_BLO,
                         (unsigned)(krow*LDA + ng*8)*2,
                         *(const float4*)p, *(const float4*)(p + 4));
        }
        __syncthreads();
        mma_chunk(c, sb, wm, wn, lane);
    }
#pragma unroll
    for (int mt = 0; mt < 2; mt++)
#pragma unroll
        for (int nt = 0; nt < 4; nt++) {
            int col = wn*32 + nt*8 + (lane & 3)*2;   // < 64
            int r0 = wm*32 + mt*16 + (lane >> 2);
            int t0 = ts[r0], t1 = ts[r0 + 8];
            if (t0 >= 0) {
                size_t base = ((size_t)(t0>>11)*NH + h)*NSEQ + (t0 & 2047);
                *(float2*)&g_vals[base*DH + col] = make_float2(c[mt][nt][0], c[mt][nt][1]);
            }
            if (t1 >= 0) {
                size_t base = ((size_t)(t1>>11)*NH + h)*NSEQ + (t1 & 2047);
                *(float2*)&g_vals[base*DH + col] = make_float2(c[mt][nt][2], c[mt][nt][3]);
            }
        }
}

// ---------------- kernel 5: causal flash attention (fp32, FFMA2) ----------------
#define QP 132
#define KP 68
#define ATTN_SMEM ((64*QP + 64*KP + 64*KP + 128*KP + 3*128) * 4)
__global__ void __launch_bounds__(256, 1)
attn_kernel() {
    extern __shared__ float sm[];
    float* Qs = sm;
    float* Ks = Qs + 64*QP;
    float* Vs = Ks + 64*KP;
    float* Ps = Vs + 64*KP;
    float* m_s = Ps + 128*KP;
    float* l_s = m_s + 128;
    float* f_s = l_s + 128;
    int bh = blockIdx.x;
    int qt = (int)(gridDim.y - 1) - (int)blockIdx.y;
    int qbase = qt * 128;
    int tid = threadIdx.x;
    int tyy = tid >> 4, txx = tid & 15;
    const float scale = 0.125f;

#pragma unroll
    for (int r = 0; r < 8; r++) {
        int id = tid + 256*r;
        int m = id >> 4, d4 = (id & 15) * 4;
        float4 v = *(const float4*)&g_q[((size_t)bh*NSEQ + qbase + m)*DH + d4];
        Qs[(d4+0)*QP + m] = v.x * scale;
        Qs[(d4+1)*QP + m] = v.y * scale;
        Qs[(d4+2)*QP + m] = v.z * scale;
        Qs[(d4+3)*QP + m] = v.w * scale;
    }
    if (tid < 128) { m_s[tid] = -1e30f; l_s[tid] = 0.f; }
    ull o2[8][2] = {};

    int ntiles = qt*2 + 2;
    for (int jt = 0; jt < ntiles; jt++) {
        __syncthreads();
#pragma unroll
        for (int r = 0; r < 4; r++) {
            int id = tid + 256*r;
            int j = id >> 4, d4 = (id & 15) * 4;
            float4 kv = *(const float4*)&g_k[((size_t)bh*NSEQ + jt*64 + j)*DH + d4];
            Ks[(d4+0)*KP + j] = kv.x;
            Ks[(d4+1)*KP + j] = kv.y;
            Ks[(d4+2)*KP + j] = kv.z;
            Ks[(d4+3)*KP + j] = kv.w;
            float4 vv = *(const float4*)&g_vals[((size_t)bh*NSEQ + jt*64 + j)*DH + d4];
            *(float4*)&Vs[j*KP + d4] = vv;
        }
        __syncthreads();
        ull s2[8][2] = {};
#pragma unroll 8
        for (int d = 0; d < 64; d++) {
            float4 a0 = *(const float4*)&Qs[d*QP + tyy*8];
            float4 a1 = *(const float4*)&Qs[d*QP + tyy*8 + 4];
            F4U2 B; B.f4 = *(const float4*)&Ks[d*KP + txx*4];
            float av[8] = {a0.x,a0.y,a0.z,a0.w,a1.x,a1.y,a1.z,a1.w};
#pragma unroll
            for (int i = 0; i < 8; i++) {
                ull aa = dup2(av[i]);
                ffma2(s2[i][0], aa, B.u2[0]);
                ffma2(s2[i][1], aa, B.u2[1]);
            }
        }
        float s[8][4];
#pragma unroll
        for (int i = 0; i < 8; i++) {
            float2 f0 = unpack2(s2[i][0]), f1 = unpack2(s2[i][1]);
            s[i][0] = f0.x; s[i][1] = f0.y; s[i][2] = f1.x; s[i][3] = f1.y;
        }
        if (jt*64 + 63 > qbase + tyy*8) {
#pragma unroll
            for (int i = 0; i < 8; i++)
#pragma unroll
                for (int j = 0; j < 4; j++)
                    if (jt*64 + txx*4 + j > qbase + tyy*8 + i) s[i][j] = -1e30f;
        }
#pragma unroll
        for (int i = 0; i < 8; i++)
            *(float4*)&Ps[(tyy*8+i)*KP + txx*4] =
                make_float4(s[i][0], s[i][1], s[i][2], s[i][3]);
        __syncthreads();
        {
            int row = tid >> 1, half = tid & 1;
            float* P = &Ps[row*KP + half*32];
            float mx = m_s[row];
#pragma unroll 8
            for (int j2 = 0; j2 < 32; j2++) mx = fmaxf(mx, P[j2]);
            mx = fmaxf(mx, __shfl_xor_sync(0xffffffffu, mx, 1));
            float sum = 0.f;
#pragma unroll 8
            for (int j2 = 0; j2 < 32; j2++) {
                float p = __expf(P[j2] - mx); P[j2] = p; sum += p;
            }
            sum += __shfl_xor_sync(0xffffffffu, sum, 1);
            if (half == 0) {
                float mo = m_s[row];
                float f = __expf(mo - mx);
                m_s[row] = mx;
                l_s[row] = l_s[row]*f + sum;
                f_s[row] = f;
            }
        }
        __syncthreads();
#pragma unroll
        for (int i = 0; i < 8; i++) {
            ull ff = dup2(f_s[tyy*8 + i]);
            mul2(o2[i][0], ff);
            mul2(o2[i][1], ff);
        }
#pragma unroll 8
        for (int jj = 0; jj < 64; jj++) {
            F4U2 B; B.f4 = *(const float4*)&Vs[jj*KP + txx*4];
#pragma unroll
            for (int i = 0; i < 8; i++) {
                ull aa = dup2(Ps[(tyy*8+i)*KP + jj]);
                ffma2(o2[i][0], aa, B.u2[0]);
                ffma2(o2[i][1], aa, B.u2[1]);
            }
        }
    }
#pragma unroll
    for (int i = 0; i < 8; i++) {
        int row = tyy*8 + i;
        float inv = 1.f / l_s[row];
        float2 f0 = unpack2(o2[i][0]), f1 = unpack2(o2[i][1]);
        float4 ov = make_float4(f0.x*inv, f0.y*inv, f1.x*inv, f1.y*inv);
        *(float4*)&g_attn[((size_t)bh*NSEQ + qbase + row)*DH + txx*4] = ov;
    }
}

// ---------------- kernel 6: output-expert GEMM via warp MMA (K=64) ----------------
__global__ void __launch_bounds__(256, 2)
outt_kernel(const float* __restrict__ oexp) {
    extern __shared__ __align__(128) char smem[];
    int he = blockIdx.x; int h = he >> 3, e = he & 7;
    int cnt = g_cnt[he];
    int start = blockIdx.y * 128;
    if (start >= cnt) return;
    int ct = blockIdx.z;                 // 16 col tiles of 64
    unsigned sb = smem_u32(smem);
    int tid = threadIdx.x, wid = tid >> 5, lane = tid & 31;
    int wm = wid & 3, wn = wid >> 2;
    int* ts = (int*)(smem + SM_TS);
    float* gts = (float*)(smem + SM_GTS);
    if (tid < 128) {
        int t = (start + tid < cnt) ? g_list[(size_t)he*TTOK + start + tid] : -1;
        ts[tid] = t;
        gts[tid] = (t >= 0) ? g_gate[(size_t)((t>>11)*NH + h)*NSEQ + (t & 2047)] : 0.f;
    }
    __syncthreads();
    const float* B = oexp + (size_t)(e*NH + h)*DH*DIMM;

    // A: gated attn [128 tok][64 dh]
#pragma unroll
    for (int r = 0; r < 4; r++) {
        int task = tid + 256*r;
        int row = task >> 3, kg = task & 7;
        int t = ts[row];
        float4 v0 = make_float4(0.f,0.f,0.f,0.f), v1 = v0;
        if (t >= 0) {
            size_t base = ((size_t)(t>>11)*NH + h)*NSEQ + (t & 2047);
            const float* p = &g_attn[base*DH + kg*8];
            v0 = *(const float4*)p; v1 = *(const float4*)(p + 4);
            float g = gts[row];
            v0.x*=g; v0.y*=g; v0.z*=g; v0.w*=g;
            v1.x*=g; v1.y*=g; v1.z*=g; v1.w*=g;
        }
        split_store8(smem + SM_AHI, smem + SM_ALO, (unsigned)(row*LDA + kg*8)*2, v0, v1);
    }
    // B: [64 k][64 n] slice of [64][1024]
#pragma unroll
    for (int r = 0; r < 2; r++) {
        int task = tid + 256*r;
        int krow = task >> 3, ng = task & 7;
        const float* p = B + (size_t)krow*DIMM + ct*64 + ng*8;
        split_store8(smem + SM_BHI, smem + SM_BLO, (unsigned)(krow*LDA + ng*8)*2,
                     *(const float4*)p, *(const float4*)(p + 4));
    }
    __syncthreads();
    float c[2][4][4] = {};
    mma_chunk(c, sb, wm, wn, lane);
#pragma unroll
    for (int mt = 0; mt < 2; mt++)
#pragma unroll
        for (int nt = 0; nt < 4; nt++) {
            int col = ct*64 + wn*32 + nt*8 + (lane & 3)*2;
            int r0 = wm*32 + mt*16 + (lane >> 2);
            int t0 = ts[r0], t1 = ts[r0 + 8];
            if (t0 >= 0) {
                size_t base = ((size_t)(t0>>11)*NH + h)*NSEQ + (t0 & 2047);
                *(float2*)&g_outh[base*DIMM + col] = make_float2(c[mt][nt][0], c[mt][nt][1]);
            }
            if (t1 >= 0) {
                size_t base = ((size_t)(t1>>11)*NH + h)*NSEQ + (t1 & 2047);
                *(float2*)&g_outh[base*DIMM + col] = make_float2(c[mt][nt][2], c[mt][nt][3]);
            }
        }
}

// ---------------- kernel 7: sum over heads ----------------
__global__ void reduce_kernel(float* __restrict__ out) {
    int idx = blockIdx.x * blockDim.x + threadIdx.x;
    const int total = TTOK * (DIMM/4);
    const float4* ph = (const float4*)g_outh;
    float4* po = (float4*)out;
    for (; idx < total; idx += gridDim.x * blockDim.x) {
        int t = idx >> 8;
        int d4 = idx & 255;
        int b_ = t >> 11, n = t & 2047;
        float4 s = make_float4(0.f,0.f,0.f,0.f);
#pragma unroll
        for (int h = 0; h < NH; h++) {
            float4 v = ph[((size_t)(b_*NH + h)*NSEQ + n)*256 + d4];
            s.x += v.x; s.y += v.y; s.z += v.z; s.w += v.w;
        }
        po[idx] = s;
    }
}

// ---------------- launch ----------------
extern "C" void kernel_launch(void* const* d_in, const int* in_sizes, int n_in,
                              void* d_out, int out_size) {
    const float* x  = (const float*)d_in[0];
    const float* wq = (const float*)d_in[1];
    const float* wk = (const float*)d_in[2];
    const float* wg = (const float*)d_in[3];
    const float* ve = (const float*)d_in[4];
    const float* oe = (const float*)d_in[5];
    float* out = (float*)d_out;

    cudaFuncSetAttribute(attn_kernel,
                         cudaFuncAttributeMaxDynamicSharedMemorySize, ATTN_SMEM);
    cudaFuncSetAttribute(projt_kernel,
                         cudaFuncAttributeMaxDynamicSharedMemorySize, TENS_SMEM);
    cudaFuncSetAttribute(valt_kernel,
                         cudaFuncAttributeMaxDynamicSharedMemorySize, TENS_SMEM);
    cudaFuncSetAttribute(outt_kernel,
                         cudaFuncAttributeMaxDynamicSharedMemorySize, TENS_SMEM);

    init_kernel<<<1, 64>>>();
    projt_kernel<<<dim3(TTOK/128, 16), 256, TENS_SMEM>>>(x, wq, wk);
    glogit_kernel<<<dim3(TTOK/128, 8), 256>>>(x, wg);
    gate_kernel<<<(TTOK*NH)/256, 256>>>();
    valt_kernel<<<dim3(NH*NE, TTOK/128), 256, TENS_SMEM>>>(x, ve);
    attn_kernel<<<dim3(BH, NSEQ/128), 256, ATTN_SMEM>>>();
    outt_kernel<<<dim3(NH*NE, TTOK/128, DIMM/64), 256, TENS_SMEM>>>(oe);
    reduce_kernel<<<2048, 256>>>(out);
}

// round 11
// speedup vs baseline: 1.9669x; 1.1983x over previous
#include <cuda_runtime.h>
#include <cuda_bf16.h>

#define BATCH 2
#define NSEQ  2048
#define DIMM  1024
#define NH    8
#define DH    64
#define NE    8
#define TTOK  (BATCH*NSEQ)     /* 4096 */
#define BH    (BATCH*NH)       /* 16 */
#define GCOLS (NH*NE)          /* 64 */

typedef unsigned long long ull;

// ---------------- warp-MMA helpers (sm_80+ PTX, works on sm_100 base) ----------------
__device__ __forceinline__ unsigned smem_u32(const void* p) {
    unsigned a;
    asm("{ .reg .u64 t; cvta.to.shared.u64 t, %1; cvt.u32.u64 %0, t; }" : "=r"(a) : "l"(p));
    return a;
}
__device__ __forceinline__ void ldsm_x4(unsigned& r0, unsigned& r1, unsigned& r2, unsigned& r3,
                                        unsigned addr) {
    asm volatile("ldmatrix.sync.aligned.m8n8.x4.shared.b16 {%0,%1,%2,%3}, [%4];"
                 : "=r"(r0), "=r"(r1), "=r"(r2), "=r"(r3) : "r"(addr));
}
__device__ __forceinline__ void ldsm_x2t(unsigned& r0, unsigned& r1, unsigned addr) {
    asm volatile("ldmatrix.sync.aligned.m8n8.x2.trans.shared.b16 {%0,%1}, [%2];"
                 : "=r"(r0), "=r"(r1) : "r"(addr));
}
__device__ __forceinline__ void mma_bf16(float* c,
                                         unsigned a0, unsigned a1, unsigned a2, unsigned a3,
                                         unsigned b0, unsigned b1) {
    asm volatile("mma.sync.aligned.m16n8k16.row.col.f32.bf16.bf16.f32 "
                 "{%0,%1,%2,%3}, {%4,%5,%6,%7}, {%8,%9}, {%0,%1,%2,%3};"
                 : "+f"(c[0]), "+f"(c[1]), "+f"(c[2]), "+f"(c[3])
                 : "r"(a0), "r"(a1), "r"(a2), "r"(a3), "r"(b0), "r"(b1));
}

// split fp32x8 into hi/lo bf16x8, store 16B each to smem (byte offsets)
__device__ __forceinline__ void split_store8(char* hi_base, char* lo_base, unsigned off,
                                             float4 v0, float4 v1) {
    float v[8] = {v0.x, v0.y, v0.z, v0.w, v1.x, v1.y, v1.z, v1.w};
    unsigned hw[4], lw[4];
#pragma unroll
    for (int p = 0; p < 4; p++) {
        __nv_bfloat16 b0 = __float2bfloat16_rn(v[2*p]);
        __nv_bfloat16 b1 = __float2bfloat16_rn(v[2*p+1]);
        __nv_bfloat162 hh = __halves2bfloat162(b0, b1);
        hw[p] = *(unsigned*)&hh;
        float l0 = v[2*p]   - __bfloat162float(b0);
        float l1 = v[2*p+1] - __bfloat162float(b1);
        __nv_bfloat162 ll = __floats2bfloat162_rn(l0, l1);
        lw[p] = *(unsigned*)&ll;
    }
    *(uint4*)(hi_base + off) = make_uint4(hw[0], hw[1], hw[2], hw[3]);
    *(uint4*)(lo_base + off) = make_uint4(lw[0], lw[1], lw[2], lw[3]);
}

// transposed scatter: element i goes to [(d0+i)*ld + row] (bf16 counts)
__device__ __forceinline__ void split_store8_T(char* hi_base, char* lo_base,
                                               int d0, int row, int ld,
                                               float4 v0, float4 v1) {
    float v[8] = {v0.x, v0.y, v0.z, v0.w, v1.x, v1.y, v1.z, v1.w};
#pragma unroll
    for (int i = 0; i < 8; i++) {
        __nv_bfloat16 h = __float2bfloat16_rn(v[i]);
        __nv_bfloat16 l = __float2bfloat16_rn(v[i] - __bfloat162float(h));
        *(__nv_bfloat16*)(hi_base + ((size_t)(d0+i)*ld + row)*2) = h;
        *(__nv_bfloat16*)(lo_base + ((size_t)(d0+i)*ld + row)*2) = l;
    }
}

// ---------------- scratch ----------------
static __device__ float g_q[BH*NSEQ*DH];
static __device__ float g_k[BH*NSEQ*DH];
static __device__ float g_gpart[8][TTOK*GCOLS];
static __device__ float g_gate[BH*NSEQ];
static __device__ int   g_cnt[NH*NE];
static __device__ int   g_list[NH*NE*TTOK];
static __device__ float g_vals[BH*NSEQ*DH];
static __device__ float g_attn[BH*NSEQ*DH];
static __device__ float g_outh[(size_t)BH*NSEQ*DIMM];

__global__ void init_kernel() {
    int i = threadIdx.x;
    if (i < NH*NE) g_cnt[i] = 0;
}

// ---------------- smem layout for GEMM-MMA kernels (bytes) ----------------
#define LDA   72
#define SM_TS   0
#define SM_GTS  512
#define SM_AHI  1024
#define SM_ALO  (SM_AHI + 128*LDA*2)
#define SM_BHI  (SM_ALO + 128*LDA*2)
#define SM_BLO  (SM_BHI + 64*LDA*2)
#define TENS_SMEM (SM_BLO + 64*LDA*2)   /* 56320 */

// warp compute over one 64-K chunk: 4 ksteps x (2m x 4n) x 3 split terms
__device__ __forceinline__ void mma_chunk(float c[2][4][4], unsigned sb,
                                          int wm, int wn, int lane) {
#pragma unroll
    for (int ks = 0; ks < 4; ks++) {
        int k0 = ks * 16;
        unsigned ah[2][4], al[2][4], bh[4][2], bl[4][2];
#pragma unroll
        for (int mt = 0; mt < 2; mt++) {
            int row = wm*32 + mt*16 + (lane & 15);
            unsigned off = (unsigned)(row*LDA + k0 + (lane >> 4)*8) * 2;
            ldsm_x4(ah[mt][0], ah[mt][1], ah[mt][2], ah[mt][3], sb + SM_AHI + off);
            ldsm_x4(al[mt][0], al[mt][1], al[mt][2], al[mt][3], sb + SM_ALO + off);
        }
#pragma unroll
        for (int nt = 0; nt < 4; nt++) {
            int n0 = wn*32 + nt*8;
            unsigned off = (unsigned)((k0 + (lane & 15))*LDA + n0) * 2;
            ldsm_x2t(bh[nt][0], bh[nt][1], sb + SM_BHI + off);
            ldsm_x2t(bl[nt][0], bl[nt][1], sb + SM_BLO + off);
        }
#pragma unroll
        for (int mt = 0; mt < 2; mt++)
#pragma unroll
            for (int nt = 0; nt < 4; nt++) {
                mma_bf16(c[mt][nt], ah[mt][0], ah[mt][1], ah[mt][2], ah[mt][3],
                         bh[nt][0], bh[nt][1]);
                mma_bf16(c[mt][nt], ah[mt][0], ah[mt][1], ah[mt][2], ah[mt][3],
                         bl[nt][0], bl[nt][1]);
                mma_bf16(c[mt][nt], al[mt][0], al[mt][1], al[mt][2], al[mt][3],
                         bh[nt][0], bh[nt][1]);
            }
    }
}

// ---------------- kernel 1: proj Q/K via warp MMA (bf16 3-term split) ----------------
__global__ void __launch_bounds__(256, 2)
projt_kernel(const float* __restrict__ x,
             const float* __restrict__ wq,
             const float* __restrict__ wk) {
    extern __shared__ __align__(128) char smem[];
    unsigned sb = smem_u32(smem);
    int tid = threadIdx.x, wid = tid >> 5, lane = tid & 31;
    int bm = blockIdx.x, bn = blockIdx.y;
    int wm = wid & 3, wn = wid >> 2;
    const float* W = (bn < 8) ? wq : wk;
    int colbase = (bn & 7) * 64;

    float c[2][4][4] = {};
    for (int ch = 0; ch < 16; ch++) {
        if (ch) __syncthreads();
#pragma unroll
        for (int r = 0; r < 4; r++) {
            int task = tid + 256*r;
            int row = task >> 3, kg = task & 7;
            const float* p = x + (size_t)(bm*128 + row)*DIMM + ch*64 + kg*8;
            split_store8(smem + SM_AHI, smem + SM_ALO,
                         (unsigned)(row*LDA + kg*8)*2,
                         *(const float4*)p, *(const float4*)(p + 4));
        }
#pragma unroll
        for (int r = 0; r < 2; r++) {
            int task = tid + 256*r;
            int krow = task >> 3, ng = task & 7;
            const float* p = W + (size_t)(ch*64 + krow)*512 + colbase + ng*8;
            split_store8(smem + SM_BHI, smem + SM_BLO,
                         (unsigned)(krow*LDA + ng*8)*2,
                         *(const float4*)p, *(const float4*)(p + 4));
        }
        __syncthreads();
        mma_chunk(c, sb, wm, wn, lane);
    }
#pragma unroll
    for (int mt = 0; mt < 2; mt++)
#pragma unroll
        for (int nt = 0; nt < 4; nt++) {
            int r0 = bm*128 + wm*32 + mt*16 + (lane >> 2);
            int col = bn*64 + wn*32 + nt*8 + (lane & 3)*2;
            int b0_ = r0 >> 11, n0_ = r0 & 2047;
            int b1_ = (r0+8) >> 11, n1_ = (r0+8) & 2047;
            float* d0;
            float* d1;
            if (col < 512) {
                d0 = &g_q[((size_t)(b0_*NH + (col >> 6))*NSEQ + n0_)*DH + (col & 63)];
                d1 = &g_q[((size_t)(b1_*NH + (col >> 6))*NSEQ + n1_)*DH + (col & 63)];
            } else {
                int c2 = col - 512;
                d0 = &g_k[((size_t)(b0_*NH + (c2 >> 6))*NSEQ + n0_)*DH + (c2 & 63)];
                d1 = &g_k[((size_t)(b1_*NH + (c2 >> 6))*NSEQ + n1_)*DH + (c2 & 63)];
            }
            *(float2*)d0 = make_float2(c[mt][nt][0], c[mt][nt][1]);
            *(float2*)d1 = make_float2(c[mt][nt][2], c[mt][nt][3]);
        }
}

// ---------------- kernel 2: fp32 gate logits (split-K, exact routing) ----------------
__global__ void glogit_kernel(const float* __restrict__ x, const float* __restrict__ wg) {
    __shared__ float As[16][132];
    __shared__ float Bs[16][68];
    int tid = threadIdx.x;
    int bm = blockIdx.x, kz = blockIdx.y;
    int ty = tid >> 4, tx = tid & 15;
    float acc[8][4] = {};
    for (int kc = 0; kc < 8; kc++) {
#pragma unroll
        for (int r = 0; r < 8; r++) {
            int idx = tid + 256*r;
            int tok = idx >> 4, k = idx & 15;
            As[k][tok] = x[(size_t)(bm*128 + tok)*DIMM + kz*128 + kc*16 + k];
        }
#pragma unroll
        for (int r = 0; r < 4; r++) {
            int idx = tid + 256*r;
            int k = idx >> 6, c2 = idx & 63;
            Bs[k][c2] = wg[(size_t)(kz*128 + kc*16 + k)*GCOLS + c2];
        }
        __syncthreads();
#pragma unroll
        for (int k = 0; k < 16; k++) {
            float a_[8], b_[4];
#pragma unroll
            for (int i = 0; i < 8; i++) a_[i] = As[k][ty*8 + i];
#pragma unroll
            for (int j = 0; j < 4; j++) b_[j] = Bs[k][tx*4 + j];
#pragma unroll
            for (int i = 0; i < 8; i++)
#pragma unroll
                for (int j = 0; j < 4; j++)
                    acc[i][j] += a_[i] * b_[j];
        }
        __syncthreads();
    }
#pragma unroll
    for (int i = 0; i < 8; i++)
#pragma unroll
        for (int j = 0; j < 4; j++)
            g_gpart[kz][(size_t)(bm*128 + ty*8 + i)*GCOLS + tx*4 + j] = acc[i][j];
}

// ---------------- kernel 3: gate sigmoid + argmax + bucket append ----------------
__global__ void gate_kernel() {
    int id = blockIdx.x * blockDim.x + threadIdx.x;
    if (id >= TTOK*NH) return;
    int t = id / NH, h = id % NH;
    float lg[NE] = {};
#pragma unroll
    for (int kz = 0; kz < 8; kz++) {
        const float* gp = &g_gpart[kz][(size_t)t*GCOLS + h*NE];
        float4 a = *(const float4*)gp, b = *(const float4*)(gp + 4);
        lg[0]+=a.x; lg[1]+=a.y; lg[2]+=a.z; lg[3]+=a.w;
        lg[4]+=b.x; lg[5]+=b.y; lg[6]+=b.z; lg[7]+=b.w;
    }
    float best = lg[0]; int be = 0;
#pragma unroll
    for (int e = 1; e < NE; e++) { if (lg[e] > best) { best = lg[e]; be = e; } }
    float gate = 1.f / (1.f + __expf(-best));
    int b_ = t >> 11, n = t & 2047;
    g_gate[(size_t)(b_*NH + h)*NSEQ + n] = gate;
    int pos = atomicAdd(&g_cnt[h*NE + be], 1);
    g_list[(size_t)(h*NE + be)*TTOK + pos] = t;
}

// ---------------- kernel 4: value-expert GEMM via warp MMA ----------------
__global__ void __launch_bounds__(256, 2)
valt_kernel(const float* __restrict__ x, const float* __restrict__ vexp) {
    extern __shared__ __align__(128) char smem[];
    int he = blockIdx.x; int h = he >> 3, e = he & 7;
    int cnt = g_cnt[he];
    int start = blockIdx.y * 128;
    if (start >= cnt) return;
    unsigned sb = smem_u32(smem);
    int tid = threadIdx.x, wid = tid >> 5, lane = tid & 31;
    int wm = wid & 3, wn = wid >> 2;
    int* ts = (int*)(smem + SM_TS);
    float* gts = (float*)(smem + SM_GTS);
    if (tid < 128) {
        int t = (start + tid < cnt) ? g_list[(size_t)he*TTOK + start + tid] : -1;
        ts[tid] = t;
        gts[tid] = (t >= 0) ? g_gate[(size_t)((t>>11)*NH + h)*NSEQ + (t & 2047)] : 0.f;
    }
    __syncthreads();
    const float* B = vexp + (size_t)(e*NH + h)*DIMM*DH;

    float c[2][4][4] = {};
    for (int ch = 0; ch < 16; ch++) {
        if (ch) __syncthreads();
#pragma unroll
        for (int r = 0; r < 4; r++) {
            int task = tid + 256*r;
            int row = task >> 3, kg = task & 7;
            int t = ts[row];
            float4 v0 = make_float4(0.f,0.f,0.f,0.f), v1 = v0;
            if (t >= 0) {
                const float* p = x + (size_t)t*DIMM + ch*64 + kg*8;
                v0 = *(const float4*)p; v1 = *(const float4*)(p + 4);
                float g = gts[row];
                v0.x*=g; v0.y*=g; v0.z*=g; v0.w*=g;
                v1.x*=g; v1.y*=g; v1.z*=g; v1.w*=g;
            }
            split_store8(smem + SM_AHI, smem + SM_ALO,
                         (unsigned)(row*LDA + kg*8)*2, v0, v1);
        }
#pragma unroll
        for (int r = 0; r < 2; r++) {
            int task = tid + 256*r;
            int krow = task >> 3, ng = task & 7;
            const float* p = B + (size_t)(ch*64 + krow)*DH + ng*8;
            split_store8(smem + SM_BHI, smem + SM_BLO,
                         (unsigned)(krow*LDA + ng*8)*2,
                         *(const float4*)p, *(const float4*)(p + 4));
        }
        __syncthreads();
        mma_chunk(c, sb, wm, wn, lane);
    }
#pragma unroll
    for (int mt = 0; mt < 2; mt++)
#pragma unroll
        for (int nt = 0; nt < 4; nt++) {
            int col = wn*32 + nt*8 + (lane & 3)*2;
            int r0 = wm*32 + mt*16 + (lane >> 2);
            int t0 = ts[r0], t1 = ts[r0 + 8];
            if (t0 >= 0) {
                size_t base = ((size_t)(t0>>11)*NH + h)*NSEQ + (t0 & 2047);
                *(float2*)&g_vals[base*DH + col] = make_float2(c[mt][nt][0], c[mt][nt][1]);
            }
            if (t1 >= 0) {
                size_t base = ((size_t)(t1>>11)*NH + h)*NSEQ + (t1 & 2047);
                *(float2*)&g_vals[base*DH + col] = make_float2(c[mt][nt][2], c[mt][nt][3]);
            }
        }
}

// ---------------- kernel 5: causal flash attention via warp MMA ----------------
// S^T = K·Q^T (A=K natural, B=Q^T staged once), softmax on Ps, O += P·V.
#define LDQT 136                         /* bf16 per row of Q^T (128 q + 8 pad) */
#define LDP  72                          /* bf16 per row for K/V/P tiles */
#define LDPS 68                          /* fp32 per row of Ps */
#define AT_QTH 0
#define AT_QTL (AT_QTH + 64*LDQT*2)
#define AT_KH  (AT_QTL + 64*LDQT*2)
#define AT_KL  (AT_KH + 64*LDP*2)
#define AT_VH  (AT_KL + 64*LDP*2)
#define AT_VL  (AT_VH + 64*LDP*2)
#define AT_PH  (AT_VL + 64*LDP*2)
#define AT_PL  (AT_PH + 128*LDP*2)
#define AT_PS  (AT_PL + 128*LDP*2)
#define AT_M   (AT_PS + 128*LDPS*4)
#define AT_L   (AT_M + 512)
#define AT_F   (AT_L + 512)
#define ATTN2_SMEM (AT_F + 512)          /* 144896 */

__global__ void __launch_bounds__(256, 1)
attn_kernel() {
    extern __shared__ __align__(128) char smem[];
    unsigned sb = smem_u32(smem);
    float* Ps  = (float*)(smem + AT_PS);
    float* m_s = (float*)(smem + AT_M);
    float* l_s = (float*)(smem + AT_L);
    float* f_s = (float*)(smem + AT_F);
    int bh = blockIdx.x;
    int qt = (int)(gridDim.y - 1) - (int)blockIdx.y;   // heavy tiles first
    int qbase = qt * 128;
    int tid = threadIdx.x, wid = tid >> 5, lane = tid & 31;
    int wm = wid & 3, wn = wid >> 2;       // O tiling: 4m x 2n
    int wmS = wid & 1, wnS = wid >> 1;     // S^T tiling: 2m(kv) x 4n(q)
    const float scale = 0.125f;

    // stage Q^T split (scaled), one time: [d][qrow]
#pragma unroll
    for (int r = 0; r < 4; r++) {
        int task = tid + 256*r;             // 1024 tasks: 128 rows x 8 kgroups
        int row = task >> 3, d0 = (task & 7)*8;
        const float* p = &g_q[((size_t)bh*NSEQ + qbase + row)*DH + d0];
        float4 v0 = *(const float4*)p, v1 = *(const float4*)(p + 4);
        v0.x*=scale; v0.y*=scale; v0.z*=scale; v0.w*=scale;
        v1.x*=scale; v1.y*=scale; v1.z*=scale; v1.w*=scale;
        split_store8_T(smem + AT_QTH, smem + AT_QTL, d0, row, LDQT, v0, v1);
    }
    if (tid < 128) { m_s[tid] = -1e30f; l_s[tid] = 0.f; }

    float o[2][4][4] = {};
    int ntiles = qt*2 + 2;
    for (int jt = 0; jt < ntiles; jt++) {
        __syncthreads();
        // stage K,V tiles (natural [kv][d], split)
#pragma unroll
        for (int r = 0; r < 2; r++) {
            int task = tid + 256*r;         // 512 tasks: 64 rows x 8 kgroups
            int j = task >> 3, d0 = (task & 7)*8;
            const float* pk = &g_k[((size_t)bh*NSEQ + jt*64 + j)*DH + d0];
            split_store8(smem + AT_KH, smem + AT_KL, (unsigned)(j*LDP + d0)*2,
                         *(const float4*)pk, *(const float4*)(pk + 4));
            const float* pv = &g_vals[((size_t)bh*NSEQ + jt*64 + j)*DH + d0];
            split_store8(smem + AT_VH, smem + AT_VL, (unsigned)(j*LDP + d0)*2,
                         *(const float4*)pv, *(const float4*)(pv + 4));
        }
        __syncthreads();
        // S^T mma: A=K [kv][d], B=Q^T [d][q]
        float s[2][4][4] = {};
#pragma unroll
        for (int ks = 0; ks < 4; ks++) {
            int k0 = ks * 16;
            unsigned ah[2][4], al[2][4], bh2[4][2], bl2[4][2];
#pragma unroll
            for (int mt = 0; mt < 2; mt++) {
                int row = wmS*32 + mt*16 + (lane & 15);
                unsigned off = (unsigned)(row*LDP + k0 + (lane >> 4)*8) * 2;
                ldsm_x4(ah[mt][0], ah[mt][1], ah[mt][2], ah[mt][3], sb + AT_KH + off);
                ldsm_x4(al[mt][0], al[mt][1], al[mt][2], al[mt][3], sb + AT_KL + off);
            }
#pragma unroll
            for (int nt = 0; nt < 4; nt++) {
                int n0 = wnS*32 + nt*8;
                unsigned off = (unsigned)((k0 + (lane & 15))*LDQT + n0) * 2;
                ldsm_x2t(bh2[nt][0], bh2[nt][1], sb + AT_QTH + off);
                ldsm_x2t(bl2[nt][0], bl2[nt][1], sb + AT_QTL + off);
            }
#pragma unroll
            for (int mt = 0; mt < 2; mt++)
#pragma unroll
                for (int nt = 0; nt < 4; nt++) {
                    mma_bf16(s[mt][nt], ah[mt][0], ah[mt][1], ah[mt][2], ah[mt][3],
                             bh2[nt][0], bh2[nt][1]);
                    mma_bf16(s[mt][nt], ah[mt][0], ah[mt][1], ah[mt][2], ah[mt][3],
                             bl2[nt][0], bl2[nt][1]);
                    mma_bf16(s[mt][nt], al[mt][0], al[mt][1], al[mt][2], al[mt][3],
                             bh2[nt][0], bh2[nt][1]);
                }
        }
        // causal mask (only diagonal-touching tiles) + store S^T -> Ps[q][kv]
        bool diag = (jt*64 + 63 > qbase);
#pragma unroll
        for (int mt = 0; mt < 2; mt++)
#pragma unroll
            for (int nt = 0; nt < 4; nt++) {
                int kvr = wmS*32 + mt*16 + (lane >> 2);
                int q0  = wnS*32 + nt*8 + (lane & 3)*2;
                if (diag) {
                    int kg = jt*64 + kvr, qg = qbase + q0;
                    if (kg > qg)       s[mt][nt][0] = -1e30f;
                    if (kg > qg+1)     s[mt][nt][1] = -1e30f;
                    if (kg+8 > qg)     s[mt][nt][2] = -1e30f;
                    if (kg+8 > qg+1)   s[mt][nt][3] = -1e30f;
                }
                Ps[q0*LDPS + kvr]       = s[mt][nt][0];
                Ps[(q0+1)*LDPS + kvr]   = s[mt][nt][1];
                Ps[q0*LDPS + kvr+8]     = s[mt][nt][2];
                Ps[(q0+1)*LDPS + kvr+8] = s[mt][nt][3];
            }
        __syncthreads();
        // online softmax (2 thr/row) + emit P as split bf16 [q][kv]
        {
            int row = tid >> 1, half = tid & 1;
            float* P = &Ps[row*LDPS + half*32];
            float mx = m_s[row];
#pragma unroll 8
            for (int j2 = 0; j2 < 32; j2++) mx = fmaxf(mx, P[j2]);
            mx = fmaxf(mx, __shfl_xor_sync(0xffffffffu, mx, 1));
            float sum = 0.f;
            __nv_bfloat162* PH2 = (__nv_bfloat162*)(smem + AT_PH + (size_t)(row*LDP + half*32)*2);
            __nv_bfloat162* PL2 = (__nv_bfloat162*)(smem + AT_PL + (size_t)(row*LDP + half*32)*2);
#pragma unroll 4
            for (int j2 = 0; j2 < 32; j2 += 2) {
                float p0 = __expf(P[j2] - mx);
                float p1 = __expf(P[j2+1] - mx);
                sum += p0 + p1;
                __nv_bfloat16 h0 = __float2bfloat16_rn(p0);
                __nv_bfloat16 h1 = __float2bfloat16_rn(p1);
                PH2[j2 >> 1] = __halves2bfloat162(h0, h1);
                PL2[j2 >> 1] = __floats2bfloat162_rn(p0 - __bfloat162float(h0),
                                                     p1 - __bfloat162float(h1));
            }
            sum += __shfl_xor_sync(0xffffffffu, sum, 1);
            if (half == 0) {
                float mo = m_s[row];
                float f = __expf(mo - mx);
                m_s[row] = mx;
                l_s[row] = l_s[row]*f + sum;
                f_s[row] = f;
            }
        }
        __syncthreads();
        // rescale O and accumulate P·V
#pragma unroll
        for (int mt = 0; mt < 2; mt++) {
            int r0 = wm*32 + mt*16 + (lane >> 2);
            float f0 = f_s[r0], f1 = f_s[r0 + 8];
#pragma unroll
            for (int nt = 0; nt < 4; nt++) {
                o[mt][nt][0] *= f0; o[mt][nt][1] *= f0;
                o[mt][nt][2] *= f1; o[mt][nt][3] *= f1;
            }
        }
#pragma unroll
        for (int ks = 0; ks < 4; ks++) {
            int k0 = ks * 16;
            unsigned ah[2][4], al[2][4], bh2[4][2], bl2[4][2];
#pragma unroll
            for (int mt = 0; mt < 2; mt++) {
                int row = wm*32 + mt*16 + (lane & 15);
                unsigned off = (unsigned)(row*LDP + k0 + (lane >> 4)*8) * 2;
                ldsm_x4(ah[mt][0], ah[mt][1], ah[mt][2], ah[mt][3], sb + AT_PH + off);
                ldsm_x4(al[mt][0], al[mt][1], al[mt][2], al[mt][3], sb + AT_PL + off);
            }
#pragma unroll
            for (int nt = 0; nt < 4; nt++) {
                int n0 = wn*32 + nt*8;
                unsigned off = (unsigned)((k0 + (lane & 15))*LDP + n0) * 2;
                ldsm_x2t(bh2[nt][0], bh2[nt][1], sb + AT_VH + off);
                ldsm_x2t(bl2[nt][0], bl2[nt][1], sb + AT_VL + off);
            }
#pragma unroll
            for (int mt = 0; mt < 2; mt++)
#pragma unroll
                for (int nt = 0; nt < 4; nt++) {
                    mma_bf16(o[mt][nt], ah[mt][0], ah[mt][1], ah[mt][2], ah[mt][3],
                             bh2[nt][0], bh2[nt][1]);
                    mma_bf16(o[mt][nt], ah[mt][0], ah[mt][1], ah[mt][2], ah[mt][3],
                             bl2[nt][0], bl2[nt][1]);
                    mma_bf16(o[mt][nt], al[mt][0], al[mt][1], al[mt][2], al[mt][3],
                             bh2[nt][0], bh2[nt][1]);
                }
        }
    }
    // epilogue: divide by l, write
#pragma unroll
    for (int mt = 0; mt < 2; mt++) {
        int r0 = wm*32 + mt*16 + (lane >> 2);
        float inv0 = 1.f / l_s[r0], inv1 = 1.f / l_s[r0 + 8];
#pragma unroll
        for (int nt = 0; nt < 4; nt++) {
            int col = wn*32 + nt*8 + (lane & 3)*2;
            *(float2*)&g_attn[((size_t)bh*NSEQ + qbase + r0)*DH + col] =
                make_float2(o[mt][nt][0]*inv0, o[mt][nt][1]*inv0);
            *(float2*)&g_attn[((size_t)bh*NSEQ + qbase + r0 + 8)*DH + col] =
                make_float2(o[mt][nt][2]*inv1, o[mt][nt][3]*inv1);
        }
    }
}

// ---------------- kernel 6: output-expert GEMM via warp MMA (K=64) ----------------
__global__ void __launch_bounds__(256, 2)
outt_kernel(const float* __restrict__ oexp) {
    extern __shared__ __align__(128) char smem[];
    int he = blockIdx.x; int h = he >> 3, e = he & 7;
    int cnt = g_cnt[he];
    int start = blockIdx.y * 128;
    if (start >= cnt) return;
    int ct = blockIdx.z;
    unsigned sb = smem_u32(smem);
    int tid = threadIdx.x, wid = tid >> 5, lane = tid & 31;
    int wm = wid & 3, wn = wid >> 2;
    int* ts = (int*)(smem + SM_TS);
    float* gts = (float*)(smem + SM_GTS);
    if (tid < 128) {
        int t = (start + tid < cnt) ? g_list[(size_t)he*TTOK + start + tid] : -1;
        ts[tid] = t;
        gts[tid] = (t >= 0) ? g_gate[(size_t)((t>>11)*NH + h)*NSEQ + (t & 2047)] : 0.f;
    }
    __syncthreads();
    const float* B = oexp + (size_t)(e*NH + h)*DH*DIMM;

#pragma unroll
    for (int r = 0; r < 4; r++) {
        int task = tid + 256*r;
        int row = task >> 3, kg = task & 7;
        int t = ts[row];
        float4 v0 = make_float4(0.f,0.f,0.f,0.f), v1 = v0;
        if (t >= 0) {
            size_t base = ((size_t)(t>>11)*NH + h)*NSEQ + (t & 2047);
            const float* p = &g_attn[base*DH + kg*8];
            v0 = *(const float4*)p; v1 = *(const float4*)(p + 4);
            float g = gts[row];
            v0.x*=g; v0.y*=g; v0.z*=g; v0.w*=g;
            v1.x*=g; v1.y*=g; v1.z*=g; v1.w*=g;
        }
        split_store8(smem + SM_AHI, smem + SM_ALO, (unsigned)(row*LDA + kg*8)*2, v0, v1);
    }
#pragma unroll
    for (int r = 0; r < 2; r++) {
        int task = tid + 256*r;
        int krow = task >> 3, ng = task & 7;
        const float* p = B + (size_t)krow*DIMM + ct*64 + ng*8;
        split_store8(smem + SM_BHI, smem + SM_BLO, (unsigned)(krow*LDA + ng*8)*2,
                     *(const float4*)p, *(const float4*)(p + 4));
    }
    __syncthreads();
    float c[2][4][4] = {};
    mma_chunk(c, sb, wm, wn, lane);
#pragma unroll
    for (int mt = 0; mt < 2; mt++)
#pragma unroll
        for (int nt = 0; nt < 4; nt++) {
            int col = ct*64 + wn*32 + nt*8 + (lane & 3)*2;
            int r0 = wm*32 + mt*16 + (lane >> 2);
            int t0 = ts[r0], t1 = ts[r0 + 8];
            if (t0 >= 0) {
                size_t base = ((size_t)(t0>>11)*NH + h)*NSEQ + (t0 & 2047);
                *(float2*)&g_outh[base*DIMM + col] = make_float2(c[mt][nt][0], c[mt][nt][1]);
            }
            if (t1 >= 0) {
                size_t base = ((size_t)(t1>>11)*NH + h)*NSEQ + (t1 & 2047);
                *(float2*)&g_outh[base*DIMM + col] = make_float2(c[mt][nt][2], c[mt][nt][3]);
            }
        }
}

// ---------------- kernel 7: sum over heads ----------------
__global__ void reduce_kernel(float* __restrict__ out) {
    int idx = blockIdx.x * blockDim.x + threadIdx.x;
    const int total = TTOK * (DIMM/4);
    const float4* ph = (const float4*)g_outh;
    float4* po = (float4*)out;
    for (; idx < total; idx += gridDim.x * blockDim.x) {
        int t = idx >> 8;
        int d4 = idx & 255;
        int b_ = t >> 11, n = t & 2047;
        float4 s = make_float4(0.f,0.f,0.f,0.f);
#pragma unroll
        for (int h = 0; h < NH; h++) {
            float4 v = ph[((size_t)(b_*NH + h)*NSEQ + n)*256 + d4];
            s.x += v.x; s.y += v.y; s.z += v.z; s.w += v.w;
        }
        po[idx] = s;
    }
}

// ---------------- launch ----------------
extern "C" void kernel_launch(void* const* d_in, const int* in_sizes, int n_in,
                              void* d_out, int out_size) {
    const float* x  = (const float*)d_in[0];
    const float* wq = (const float*)d_in[1];
    const float* wk = (const float*)d_in[2];
    const float* wg = (const float*)d_in[3];
    const float* ve = (const float*)d_in[4];
    const float* oe = (const float*)d_in[5];
    float* out = (float*)d_out;

    cudaFuncSetAttribute(attn_kernel,
                         cudaFuncAttributeMaxDynamicSharedMemorySize, ATTN2_SMEM);
    cudaFuncSetAttribute(projt_kernel,
                         cudaFuncAttributeMaxDynamicSharedMemorySize, TENS_SMEM);
    cudaFuncSetAttribute(valt_kernel,
                         cudaFuncAttributeMaxDynamicSharedMemorySize, TENS_SMEM);
    cudaFuncSetAttribute(outt_kernel,
                         cudaFuncAttributeMaxDynamicSharedMemorySize, TENS_SMEM);

    init_kernel<<<1, 64>>>();
    projt_kernel<<<dim3(TTOK/128, 16), 256, TENS_SMEM>>>(x, wq, wk);
    glogit_kernel<<<dim3(TTOK/128, 8), 256>>>(x, wg);
    gate_kernel<<<(TTOK*NH)/256, 256>>>();
    valt_kernel<<<dim3(NH*NE, TTOK/128), 256, TENS_SMEM>>>(x, ve);
    attn_kernel<<<dim3(BH, NSEQ/128), 256, ATTN2_SMEM>>>();
    outt_kernel<<<dim3(NH*NE, TTOK/128, DIMM/64), 256, TENS_SMEM>>>(oe);
    reduce_kernel<<<2048, 256>>>(out);
}

// round 14
// speedup vs baseline: 2.1638x; 1.1001x over previous
#include <cuda_runtime.h>
#include <cuda_bf16.h>

#define BATCH 2
#define NSEQ  2048
#define DIMM  1024
#define NH    8
#define DH    64
#define NE    8
#define TTOK  (BATCH*NSEQ)     /* 4096 */
#define BH    (BATCH*NH)       /* 16 */
#define GCOLS (NH*NE)          /* 64 */

typedef unsigned long long ull;

// ---------------- warp-MMA helpers (sm_80+ PTX, works on sm_100 base) ----------------
__device__ __forceinline__ unsigned smem_u32(const void* p) {
    unsigned a;
    asm("{ .reg .u64 t; cvta.to.shared.u64 t, %1; cvt.u32.u64 %0, t; }" : "=r"(a) : "l"(p));
    return a;
}
__device__ __forceinline__ void ldsm_x4(unsigned& r0, unsigned& r1, unsigned& r2, unsigned& r3,
                                        unsigned addr) {
    asm volatile("ldmatrix.sync.aligned.m8n8.x4.shared.b16 {%0,%1,%2,%3}, [%4];"
                 : "=r"(r0), "=r"(r1), "=r"(r2), "=r"(r3) : "r"(addr));
}
__device__ __forceinline__ void ldsm_x2t(unsigned& r0, unsigned& r1, unsigned addr) {
    asm volatile("ldmatrix.sync.aligned.m8n8.x2.trans.shared.b16 {%0,%1}, [%2];"
                 : "=r"(r0), "=r"(r1) : "r"(addr));
}
__device__ __forceinline__ void mma_bf16(float* c,
                                         unsigned a0, unsigned a1, unsigned a2, unsigned a3,
                                         unsigned b0, unsigned b1) {
    asm volatile("mma.sync.aligned.m16n8k16.row.col.f32.bf16.bf16.f32 "
                 "{%0,%1,%2,%3}, {%4,%5,%6,%7}, {%8,%9}, {%0,%1,%2,%3};"
                 : "+f"(c[0]), "+f"(c[1]), "+f"(c[2]), "+f"(c[3])
                 : "r"(a0), "r"(a1), "r"(a2), "r"(a3), "r"(b0), "r"(b1));
}

// split fp32x8 into hi/lo bf16x8, store 16B each to smem (byte offsets)
__device__ __forceinline__ void split_store8(char* hi_base, char* lo_base, unsigned off,
                                             float4 v0, float4 v1) {
    float v[8] = {v0.x, v0.y, v0.z, v0.w, v1.x, v1.y, v1.z, v1.w};
    unsigned hw[4], lw[4];
#pragma unroll
    for (int p = 0; p < 4; p++) {
        __nv_bfloat16 b0 = __float2bfloat16_rn(v[2*p]);
        __nv_bfloat16 b1 = __float2bfloat16_rn(v[2*p+1]);
        __nv_bfloat162 hh = __halves2bfloat162(b0, b1);
        hw[p] = *(unsigned*)&hh;
        float l0 = v[2*p]   - __bfloat162float(b0);
        float l1 = v[2*p+1] - __bfloat162float(b1);
        __nv_bfloat162 ll = __floats2bfloat162_rn(l0, l1);
        lw[p] = *(unsigned*)&ll;
    }
    *(uint4*)(hi_base + off) = make_uint4(hw[0], hw[1], hw[2], hw[3]);
    *(uint4*)(lo_base + off) = make_uint4(lw[0], lw[1], lw[2], lw[3]);
}

// transposed scatter: element i goes to [(d0+i)*ld + row] (bf16 counts)
__device__ __forceinline__ void split_store8_T(char* hi_base, char* lo_base,
                                               int d0, int row, int ld,
                                               float4 v0, float4 v1) {
    float v[8] = {v0.x, v0.y, v0.z, v0.w, v1.x, v1.y, v1.z, v1.w};
#pragma unroll
    for (int i = 0; i < 8; i++) {
        __nv_bfloat16 h = __float2bfloat16_rn(v[i]);
        __nv_bfloat16 l = __float2bfloat16_rn(v[i] - __bfloat162float(h));
        *(__nv_bfloat16*)(hi_base + ((size_t)(d0+i)*ld + row)*2) = h;
        *(__nv_bfloat16*)(lo_base + ((size_t)(d0+i)*ld + row)*2) = l;
    }
}

// ---------------- scratch ----------------
static __device__ float g_q[BH*NSEQ*DH];
static __device__ float g_k[BH*NSEQ*DH];
static __device__ float g_gpart[8][TTOK*GCOLS];
static __device__ float g_gate[BH*NSEQ];
static __device__ int   g_cnt[NH*NE];
static __device__ int   g_list[NH*NE*TTOK];
static __device__ float g_vals[BH*NSEQ*DH];
static __device__ float g_attn[BH*NSEQ*DH];
static __device__ float g_outh[(size_t)BH*NSEQ*DIMM];

__global__ void init_kernel() {
    int i = threadIdx.x;
    if (i < NH*NE) g_cnt[i] = 0;
}

// ---------------- smem layout for GEMM-MMA kernels (bytes) ----------------
#define LDA   72
#define SM_TS   0
#define SM_GTS  512
#define SM_AHI  1024
#define SM_ALO  (SM_AHI + 128*LDA*2)
#define SM_BHI  (SM_ALO + 128*LDA*2)
#define SM_BLO  (SM_BHI + 64*LDA*2)
#define TENS_SMEM (SM_BLO + 64*LDA*2)   /* 56320 */

// warp compute over one 64-K chunk: 4 ksteps x (2m x 4n) x 3 split terms
__device__ __forceinline__ void mma_chunk(float c[2][4][4], unsigned sb,
                                          int wm, int wn, int lane) {
#pragma unroll
    for (int ks = 0; ks < 4; ks++) {
        int k0 = ks * 16;
        unsigned ah[2][4], al[2][4], bh[4][2], bl[4][2];
#pragma unroll
        for (int mt = 0; mt < 2; mt++) {
            int row = wm*32 + mt*16 + (lane & 15);
            unsigned off = (unsigned)(row*LDA + k0 + (lane >> 4)*8) * 2;
            ldsm_x4(ah[mt][0], ah[mt][1], ah[mt][2], ah[mt][3], sb + SM_AHI + off);
            ldsm_x4(al[mt][0], al[mt][1], al[mt][2], al[mt][3], sb + SM_ALO + off);
        }
#pragma unroll
        for (int nt = 0; nt < 4; nt++) {
            int n0 = wn*32 + nt*8;
            unsigned off = (unsigned)((k0 + (lane & 15))*LDA + n0) * 2;
            ldsm_x2t(bh[nt][0], bh[nt][1], sb + SM_BHI + off);
            ldsm_x2t(bl[nt][0], bl[nt][1], sb + SM_BLO + off);
        }
#pragma unroll
        for (int mt = 0; mt < 2; mt++)
#pragma unroll
            for (int nt = 0; nt < 4; nt++) {
                mma_bf16(c[mt][nt], ah[mt][0], ah[mt][1], ah[mt][2], ah[mt][3],
                         bh[nt][0], bh[nt][1]);
                mma_bf16(c[mt][nt], ah[mt][0], ah[mt][1], ah[mt][2], ah[mt][3],
                         bl[nt][0], bl[nt][1]);
                mma_bf16(c[mt][nt], al[mt][0], al[mt][1], al[mt][2], al[mt][3],
                         bh[nt][0], bh[nt][1]);
            }
    }
}

// ---------------- kernel 1: proj Q/K via warp MMA (bf16 3-term split) ----------------
__global__ void __launch_bounds__(256, 2)
projt_kernel(const float* __restrict__ x,
             const float* __restrict__ wq,
             const float* __restrict__ wk) {
    extern __shared__ __align__(128) char smem[];
    unsigned sb = smem_u32(smem);
    int tid = threadIdx.x, wid = tid >> 5, lane = tid & 31;
    int bm = blockIdx.x, bn = blockIdx.y;
    int wm = wid & 3, wn = wid >> 2;
    const float* W = (bn < 8) ? wq : wk;
    int colbase = (bn & 7) * 64;

    float c[2][4][4] = {};
    for (int ch = 0; ch < 16; ch++) {
        if (ch) __syncthreads();
#pragma unroll
        for (int r = 0; r < 4; r++) {
            int task = tid + 256*r;
            int row = task >> 3, kg = task & 7;
            const float* p = x + (size_t)(bm*128 + row)*DIMM + ch*64 + kg*8;
            split_store8(smem + SM_AHI, smem + SM_ALO,
                         (unsigned)(row*LDA + kg*8)*2,
                         *(const float4*)p, *(const float4*)(p + 4));
        }
#pragma unroll
        for (int r = 0; r < 2; r++) {
            int task = tid + 256*r;
            int krow = task >> 3, ng = task & 7;
            const float* p = W + (size_t)(ch*64 + krow)*512 + colbase + ng*8;
            split_store8(smem + SM_BHI, smem + SM_BLO,
                         (unsigned)(krow*LDA + ng*8)*2,
                         *(const float4*)p, *(const float4*)(p + 4));
        }
        __syncthreads();
        mma_chunk(c, sb, wm, wn, lane);
    }
#pragma unroll
    for (int mt = 0; mt < 2; mt++)
#pragma unroll
        for (int nt = 0; nt < 4; nt++) {
            int r0 = bm*128 + wm*32 + mt*16 + (lane >> 2);
            int col = bn*64 + wn*32 + nt*8 + (lane & 3)*2;
            int b0_ = r0 >> 11, n0_ = r0 & 2047;
            int b1_ = (r0+8) >> 11, n1_ = (r0+8) & 2047;
            float* d0;
            float* d1;
            if (col < 512) {
                d0 = &g_q[((size_t)(b0_*NH + (col >> 6))*NSEQ + n0_)*DH + (col & 63)];
                d1 = &g_q[((size_t)(b1_*NH + (col >> 6))*NSEQ + n1_)*DH + (col & 63)];
            } else {
                int c2 = col - 512;
                d0 = &g_k[((size_t)(b0_*NH + (c2 >> 6))*NSEQ + n0_)*DH + (c2 & 63)];
                d1 = &g_k[((size_t)(b1_*NH + (c2 >> 6))*NSEQ + n1_)*DH + (c2 & 63)];
            }
            *(float2*)d0 = make_float2(c[mt][nt][0], c[mt][nt][1]);
            *(float2*)d1 = make_float2(c[mt][nt][2], c[mt][nt][3]);
        }
}

// ---------------- kernel 2: fp32 gate logits (split-K, exact routing) ----------------
__global__ void glogit_kernel(const float* __restrict__ x, const float* __restrict__ wg) {
    __shared__ float As[16][132];
    __shared__ float Bs[16][68];
    int tid = threadIdx.x;
    int bm = blockIdx.x, kz = blockIdx.y;
    int ty = tid >> 4, tx = tid & 15;
    float acc[8][4] = {};
    for (int kc = 0; kc < 8; kc++) {
#pragma unroll
        for (int r = 0; r < 8; r++) {
            int idx = tid + 256*r;
            int tok = idx >> 4, k = idx & 15;
            As[k][tok] = x[(size_t)(bm*128 + tok)*DIMM + kz*128 + kc*16 + k];
        }
#pragma unroll
        for (int r = 0; r < 4; r++) {
            int idx = tid + 256*r;
            int k = idx >> 6, c2 = idx & 63;
            Bs[k][c2] = wg[(size_t)(kz*128 + kc*16 + k)*GCOLS + c2];
        }
        __syncthreads();
#pragma unroll
        for (int k = 0; k < 16; k++) {
            float a_[8], b_[4];
#pragma unroll
            for (int i = 0; i < 8; i++) a_[i] = As[k][ty*8 + i];
#pragma unroll
            for (int j = 0; j < 4; j++) b_[j] = Bs[k][tx*4 + j];
#pragma unroll
            for (int i = 0; i < 8; i++)
#pragma unroll
                for (int j = 0; j < 4; j++)
                    acc[i][j] += a_[i] * b_[j];
        }
        __syncthreads();
    }
#pragma unroll
    for (int i = 0; i < 8; i++)
#pragma unroll
        for (int j = 0; j < 4; j++)
            g_gpart[kz][(size_t)(bm*128 + ty*8 + i)*GCOLS + tx*4 + j] = acc[i][j];
}

// ---------------- kernel 3: gate sigmoid + argmax + bucket append ----------------
__global__ void gate_kernel() {
    int id = blockIdx.x * blockDim.x + threadIdx.x;
    if (id >= TTOK*NH) return;
    int t = id / NH, h = id % NH;
    float lg[NE] = {};
#pragma unroll
    for (int kz = 0; kz < 8; kz++) {
        const float* gp = &g_gpart[kz][(size_t)t*GCOLS + h*NE];
        float4 a = *(const float4*)gp, b = *(const float4*)(gp + 4);
        lg[0]+=a.x; lg[1]+=a.y; lg[2]+=a.z; lg[3]+=a.w;
        lg[4]+=b.x; lg[5]+=b.y; lg[6]+=b.z; lg[7]+=b.w;
    }
    float best = lg[0]; int be = 0;
#pragma unroll
    for (int e = 1; e < NE; e++) { if (lg[e] > best) { best = lg[e]; be = e; } }
    float gate = 1.f / (1.f + __expf(-best));
    int b_ = t >> 11, n = t & 2047;
    g_gate[(size_t)(b_*NH + h)*NSEQ + n] = gate;
    int pos = atomicAdd(&g_cnt[h*NE + be], 1);
    g_list[(size_t)(h*NE + be)*TTOK + pos] = t;
}

// ---------------- kernel 4: value-expert GEMM via warp MMA ----------------
__global__ void __launch_bounds__(256, 2)
valt_kernel(const float* __restrict__ x, const float* __restrict__ vexp) {
    extern __shared__ __align__(128) char smem[];
    int he = blockIdx.x; int h = he >> 3, e = he & 7;
    int cnt = g_cnt[he];
    int start = blockIdx.y * 128;
    if (start >= cnt) return;
    unsigned sb = smem_u32(smem);
    int tid = threadIdx.x, wid = tid >> 5, lane = tid & 31;
    int wm = wid & 3, wn = wid >> 2;
    int* ts = (int*)(smem + SM_TS);
    float* gts = (float*)(smem + SM_GTS);
    if (tid < 128) {
        int t = (start + tid < cnt) ? g_list[(size_t)he*TTOK + start + tid] : -1;
        ts[tid] = t;
        gts[tid] = (t >= 0) ? g_gate[(size_t)((t>>11)*NH + h)*NSEQ + (t & 2047)] : 0.f;
    }
    __syncthreads();
    const float* B = vexp + (size_t)(e*NH + h)*DIMM*DH;

    float c[2][4][4] = {};
    for (int ch = 0; ch < 16; ch++) {
        if (ch) __syncthreads();
#pragma unroll
        for (int r = 0; r < 4; r++) {
            int task = tid + 256*r;
            int row = task >> 3, kg = task & 7;
            int t = ts[row];
            float4 v0 = make_float4(0.f,0.f,0.f,0.f), v1 = v0;
            if (t >= 0) {
                const float* p = x + (size_t)t*DIMM + ch*64 + kg*8;
                v0 = *(const float4*)p; v1 = *(const float4*)(p + 4);
                float g = gts[row];
                v0.x*=g; v0.y*=g; v0.z*=g; v0.w*=g;
                v1.x*=g; v1.y*=g; v1.z*=g; v1.w*=g;
            }
            split_store8(smem + SM_AHI, smem + SM_ALO,
                         (unsigned)(row*LDA + kg*8)*2, v0, v1);
        }
#pragma unroll
        for (int r = 0; r < 2; r++) {
            int task = tid + 256*r;
            int krow = task >> 3, ng = task & 7;
            const float* p = B + (size_t)(ch*64 + krow)*DH + ng*8;
            split_store8(smem + SM_BHI, smem + SM_BLO,
                         (unsigned)(krow*LDA + ng*8)*2,
                         *(const float4*)p, *(const float4*)(p + 4));
        }
        __syncthreads();
        mma_chunk(c, sb, wm, wn, lane);
    }
#pragma unroll
    for (int mt = 0; mt < 2; mt++)
#pragma unroll
        for (int nt = 0; nt < 4; nt++) {
            int col = wn*32 + nt*8 + (lane & 3)*2;
            int r0 = wm*32 + mt*16 + (lane >> 2);
            int t0 = ts[r0], t1 = ts[r0 + 8];
            if (t0 >= 0) {
                size_t base = ((size_t)(t0>>11)*NH + h)*NSEQ + (t0 & 2047);
                *(float2*)&g_vals[base*DH + col] = make_float2(c[mt][nt][0], c[mt][nt][1]);
            }
            if (t1 >= 0) {
                size_t base = ((size_t)(t1>>11)*NH + h)*NSEQ + (t1 & 2047);
                *(float2*)&g_vals[base*DH + col] = make_float2(c[mt][nt][2], c[mt][nt][3]);
            }
        }
}

// ---------------- kernel 5: causal flash attention via warp MMA (R11 version) ----------------
#define LDQT 136
#define LDP  72
#define LDPS 68
#define AT_QTH 0
#define AT_QTL (AT_QTH + 64*LDQT*2)
#define AT_KH  (AT_QTL + 64*LDQT*2)
#define AT_KL  (AT_KH + 64*LDP*2)
#define AT_VH  (AT_KL + 64*LDP*2)
#define AT_VL  (AT_VH + 64*LDP*2)
#define AT_PH  (AT_VL + 64*LDP*2)
#define AT_PL  (AT_PH + 128*LDP*2)
#define AT_PS  (AT_PL + 128*LDP*2)
#define AT_M   (AT_PS + 128*LDPS*4)
#define AT_L   (AT_M + 512)
#define AT_F   (AT_L + 512)
#define ATTN2_SMEM (AT_F + 512)          /* 144896 */

__global__ void __launch_bounds__(256, 1)
attn_kernel() {
    extern __shared__ __align__(128) char smem[];
    unsigned sb = smem_u32(smem);
    float* Ps  = (float*)(smem + AT_PS);
    float* m_s = (float*)(smem + AT_M);
    float* l_s = (float*)(smem + AT_L);
    float* f_s = (float*)(smem + AT_F);
    int bh = blockIdx.x;
    int qt = (int)(gridDim.y - 1) - (int)blockIdx.y;   // heavy tiles first
    int qbase = qt * 128;
    int tid = threadIdx.x, wid = tid >> 5, lane = tid & 31;
    int wm = wid & 3, wn = wid >> 2;       // O tiling: 4m x 2n
    int wmS = wid & 1, wnS = wid >> 1;     // S^T tiling: 2m(kv) x 4n(q)
    const float scale = 0.125f;

    // stage Q^T split (scaled), one time: [d][qrow]
#pragma unroll
    for (int r = 0; r < 4; r++) {
        int task = tid + 256*r;
        int row = task >> 3, d0 = (task & 7)*8;
        const float* p = &g_q[((size_t)bh*NSEQ + qbase + row)*DH + d0];
        float4 v0 = *(const float4*)p, v1 = *(const float4*)(p + 4);
        v0.x*=scale; v0.y*=scale; v0.z*=scale; v0.w*=scale;
        v1.x*=scale; v1.y*=scale; v1.z*=scale; v1.w*=scale;
        split_store8_T(smem + AT_QTH, smem + AT_QTL, d0, row, LDQT, v0, v1);
    }
    if (tid < 128) { m_s[tid] = -1e30f; l_s[tid] = 0.f; }

    float o[2][4][4] = {};
    int ntiles = qt*2 + 2;
    for (int jt = 0; jt < ntiles; jt++) {
        __syncthreads();
        // stage K,V tiles (natural [kv][d], split)
#pragma unroll
        for (int r = 0; r < 2; r++) {
            int task = tid + 256*r;
            int j = task >> 3, d0 = (task & 7)*8;
            const float* pk = &g_k[((size_t)bh*NSEQ + jt*64 + j)*DH + d0];
            split_store8(smem + AT_KH, smem + AT_KL, (unsigned)(j*LDP + d0)*2,
                         *(const float4*)pk, *(const float4*)(pk + 4));
            const float* pv = &g_vals[((size_t)bh*NSEQ + jt*64 + j)*DH + d0];
            split_store8(smem + AT_VH, smem + AT_VL, (unsigned)(j*LDP + d0)*2,
                         *(const float4*)pv, *(const float4*)(pv + 4));
        }
        __syncthreads();
        // S^T mma: A=K [kv][d], B=Q^T [d][q]
        float s[2][4][4] = {};
#pragma unroll
        for (int ks = 0; ks < 4; ks++) {
            int k0 = ks * 16;
            unsigned ah[2][4], al[2][4], bh2[4][2], bl2[4][2];
#pragma unroll
            for (int mt = 0; mt < 2; mt++) {
                int row = wmS*32 + mt*16 + (lane & 15);
                unsigned off = (unsigned)(row*LDP + k0 + (lane >> 4)*8) * 2;
                ldsm_x4(ah[mt][0], ah[mt][1], ah[mt][2], ah[mt][3], sb + AT_KH + off);
                ldsm_x4(al[mt][0], al[mt][1], al[mt][2], al[mt][3], sb + AT_KL + off);
            }
#pragma unroll
            for (int nt = 0; nt < 4; nt++) {
                int n0 = wnS*32 + nt*8;
                unsigned off = (unsigned)((k0 + (lane & 15))*LDQT + n0) * 2;
                ldsm_x2t(bh2[nt][0], bh2[nt][1], sb + AT_QTH + off);
                ldsm_x2t(bl2[nt][0], bl2[nt][1], sb + AT_QTL + off);
            }
#pragma unroll
            for (int mt = 0; mt < 2; mt++)
#pragma unroll
                for (int nt = 0; nt < 4; nt++) {
                    mma_bf16(s[mt][nt], ah[mt][0], ah[mt][1], ah[mt][2], ah[mt][3],
                             bh2[nt][0], bh2[nt][1]);
                    mma_bf16(s[mt][nt], ah[mt][0], ah[mt][1], ah[mt][2], ah[mt][3],
                             bl2[nt][0], bl2[nt][1]);
                    mma_bf16(s[mt][nt], al[mt][0], al[mt][1], al[mt][2], al[mt][3],
                             bh2[nt][0], bh2[nt][1]);
                }
        }
        // causal mask + store S^T -> Ps[q][kv]
        bool diag = (jt*64 + 63 > qbase);
#pragma unroll
        for (int mt = 0; mt < 2; mt++)
#pragma unroll
            for (int nt = 0; nt < 4; nt++) {
                int kvr = wmS*32 + mt*16 + (lane >> 2);
                int q0  = wnS*32 + nt*8 + (lane & 3)*2;
                if (diag) {
                    int kg = jt*64 + kvr, qg = qbase + q0;
                    if (kg > qg)       s[mt][nt][0] = -1e30f;
                    if (kg > qg+1)     s[mt][nt][1] = -1e30f;
                    if (kg+8 > qg)     s[mt][nt][2] = -1e30f;
                    if (kg+8 > qg+1)   s[mt][nt][3] = -1e30f;
                }
                Ps[q0*LDPS + kvr]       = s[mt][nt][0];
                Ps[(q0+1)*LDPS + kvr]   = s[mt][nt][1];
                Ps[q0*LDPS + kvr+8]     = s[mt][nt][2];
                Ps[(q0+1)*LDPS + kvr+8] = s[mt][nt][3];
            }
        __syncthreads();
        // online softmax (2 thr/row) + emit P as split bf16 [q][kv]
        {
            int row = tid >> 1, half = tid & 1;
            float* P = &Ps[row*LDPS + half*32];
            float mx = m_s[row];
#pragma unroll 8
            for (int j2 = 0; j2 < 32; j2++) mx = fmaxf(mx, P[j2]);
            mx = fmaxf(mx, __shfl_xor_sync(0xffffffffu, mx, 1));
            float sum = 0.f;
            __nv_bfloat162* PH2 = (__nv_bfloat162*)(smem + AT_PH + (size_t)(row*LDP + half*32)*2);
            __nv_bfloat162* PL2 = (__nv_bfloat162*)(smem + AT_PL + (size_t)(row*LDP + half*32)*2);
#pragma unroll 4
            for (int j2 = 0; j2 < 32; j2 += 2) {
                float p0 = __expf(P[j2] - mx);
                float p1 = __expf(P[j2+1] - mx);
                sum += p0 + p1;
                __nv_bfloat16 h0 = __float2bfloat16_rn(p0);
                __nv_bfloat16 h1 = __float2bfloat16_rn(p1);
                PH2[j2 >> 1] = __halves2bfloat162(h0, h1);
                PL2[j2 >> 1] = __floats2bfloat162_rn(p0 - __bfloat162float(h0),
                                                     p1 - __bfloat162float(h1));
            }
            sum += __shfl_xor_sync(0xffffffffu, sum, 1);
            if (half == 0) {
                float mo = m_s[row];
                float f = __expf(mo - mx);
                m_s[row] = mx;
                l_s[row] = l_s[row]*f + sum;
                f_s[row] = f;
            }
        }
        __syncthreads();
        // rescale O and accumulate P·V
#pragma unroll
        for (int mt = 0; mt < 2; mt++) {
            int r0 = wm*32 + mt*16 + (lane >> 2);
            float f0 = f_s[r0], f1 = f_s[r0 + 8];
#pragma unroll
            for (int nt = 0; nt < 4; nt++) {
                o[mt][nt][0] *= f0; o[mt][nt][1] *= f0;
                o[mt][nt][2] *= f1; o[mt][nt][3] *= f1;
            }
        }
#pragma unroll
        for (int ks = 0; ks < 4; ks++) {
            int k0 = ks * 16;
            unsigned ah[2][4], al[2][4], bh2[4][2], bl2[4][2];
#pragma unroll
            for (int mt = 0; mt < 2; mt++) {
                int row = wm*32 + mt*16 + (lane & 15);
                unsigned off = (unsigned)(row*LDP + k0 + (lane >> 4)*8) * 2;
                ldsm_x4(ah[mt][0], ah[mt][1], ah[mt][2], ah[mt][3], sb + AT_PH + off);
                ldsm_x4(al[mt][0], al[mt][1], al[mt][2], al[mt][3], sb + AT_PL + off);
            }
#pragma unroll
            for (int nt = 0; nt < 4; nt++) {
                int n0 = wn*32 + nt*8;
                unsigned off = (unsigned)((k0 + (lane & 15))*LDP + n0) * 2;
                ldsm_x2t(bh2[nt][0], bh2[nt][1], sb + AT_VH + off);
                ldsm_x2t(bl2[nt][0], bl2[nt][1], sb + AT_VL + off);
            }
#pragma unroll
            for (int mt = 0; mt < 2; mt++)
#pragma unroll
                for (int nt = 0; nt < 4; nt++) {
                    mma_bf16(o[mt][nt], ah[mt][0], ah[mt][1], ah[mt][2], ah[mt][3],
                             bh2[nt][0], bh2[nt][1]);
                    mma_bf16(o[mt][nt], ah[mt][0], ah[mt][1], ah[mt][2], ah[mt][3],
                             bl2[nt][0], bl2[nt][1]);
                    mma_bf16(o[mt][nt], al[mt][0], al[mt][1], al[mt][2], al[mt][3],
                             bh2[nt][0], bh2[nt][1]);
                }
        }
    }
    // epilogue: divide by l, write
#pragma unroll
    for (int mt = 0; mt < 2; mt++) {
        int r0 = wm*32 + mt*16 + (lane >> 2);
        float inv0 = 1.f / l_s[r0], inv1 = 1.f / l_s[r0 + 8];
#pragma unroll
        for (int nt = 0; nt < 4; nt++) {
            int col = wn*32 + nt*8 + (lane & 3)*2;
            *(float2*)&g_attn[((size_t)bh*NSEQ + qbase + r0)*DH + col] =
                make_float2(o[mt][nt][0]*inv0, o[mt][nt][1]*inv0);
            *(float2*)&g_attn[((size_t)bh*NSEQ + qbase + r0 + 8)*DH + col] =
                make_float2(o[mt][nt][2]*inv1, o[mt][nt][3]*inv1);
        }
    }
}

// ---------------- kernel 6: output-expert GEMM via warp MMA, 4 col-tiles/block ----------------
__global__ void __launch_bounds__(256, 2)
outt_kernel(const float* __restrict__ oexp) {
    extern __shared__ __align__(128) char smem[];
    int he = blockIdx.x; int h = he >> 3, e = he & 7;
    int cnt = g_cnt[he];
    int start = blockIdx.y * 128;
    if (start >= cnt) return;
    int ct0 = blockIdx.z * 4;            // 4 blocks x 4 tiles of 64 cols
    unsigned sb = smem_u32(smem);
    int tid = threadIdx.x, wid = tid >> 5, lane = tid & 31;
    int wm = wid & 3, wn = wid >> 2;
    int* ts = (int*)(smem + SM_TS);
    float* gts = (float*)(smem + SM_GTS);
    if (tid < 128) {
        int t = (start + tid < cnt) ? g_list[(size_t)he*TTOK + start + tid] : -1;
        ts[tid] = t;
        gts[tid] = (t >= 0) ? g_gate[(size_t)((t>>11)*NH + h)*NSEQ + (t & 2047)] : 0.f;
    }
    __syncthreads();
    const float* B = oexp + (size_t)(e*NH + h)*DH*DIMM;

    // stage A once (gated attn [128 tok][64 dh])
#pragma unroll
    for (int r = 0; r < 4; r++) {
        int task = tid + 256*r;
        int row = task >> 3, kg = task & 7;
        int t = ts[row];
        float4 v0 = make_float4(0.f,0.f,0.f,0.f), v1 = v0;
        if (t >= 0) {
            size_t base = ((size_t)(t>>11)*NH + h)*NSEQ + (t & 2047);
            const float* p = &g_attn[base*DH + kg*8];
            v0 = *(const float4*)p; v1 = *(const float4*)(p + 4);
            float g = gts[row];
            v0.x*=g; v0.y*=g; v0.z*=g; v0.w*=g;
            v1.x*=g; v1.y*=g; v1.z*=g; v1.w*=g;
        }
        split_store8(smem + SM_AHI, smem + SM_ALO, (unsigned)(row*LDA + kg*8)*2, v0, v1);
    }

    for (int i = 0; i < 4; i++) {
        int ct = ct0 + i;
        __syncthreads();                 // A visible / previous B consumed
#pragma unroll
        for (int r = 0; r < 2; r++) {
            int task = tid + 256*r;
            int krow = task >> 3, ng = task & 7;
            const float* p = B + (size_t)krow*DIMM + ct*64 + ng*8;
            split_store8(smem + SM_BHI, smem + SM_BLO, (unsigned)(krow*LDA + ng*8)*2,
                         *(const float4*)p, *(const float4*)(p + 4));
        }
        __syncthreads();
        float c[2][4][4] = {};
        mma_chunk(c, sb, wm, wn, lane);
#pragma unroll
        for (int mt = 0; mt < 2; mt++)
#pragma unroll
            for (int nt = 0; nt < 4; nt++) {
                int col = ct*64 + wn*32 + nt*8 + (lane & 3)*2;
                int r0 = wm*32 + mt*16 + (lane >> 2);
                int t0 = ts[r0], t1 = ts[r0 + 8];
                if (t0 >= 0) {
                    size_t base = ((size_t)(t0>>11)*NH + h)*NSEQ + (t0 & 2047);
                    *(float2*)&g_outh[base*DIMM + col] = make_float2(c[mt][nt][0], c[mt][nt][1]);
                }
                if (t1 >= 0) {
                    size_t base = ((size_t)(t1>>11)*NH + h)*NSEQ + (t1 & 2047);
                    *(float2*)&g_outh[base*DIMM + col] = make_float2(c[mt][nt][2], c[mt][nt][3]);
                }
            }
    }
}

// ---------------- kernel 7: sum over heads ----------------
__global__ void reduce_kernel(float* __restrict__ out) {
    int idx = blockIdx.x * blockDim.x + threadIdx.x;
    const int total = TTOK * (DIMM/4);
    const float4* ph = (const float4*)g_outh;
    float4* po = (float4*)out;
    for (; idx < total; idx += gridDim.x * blockDim.x) {
        int t = idx >> 8;
        int d4 = idx & 255;
        int b_ = t >> 11, n = t & 2047;
        float4 s = make_float4(0.f,0.f,0.f,0.f);
#pragma unroll
        for (int h = 0; h < NH; h++) {
            float4 v = ph[((size_t)(b_*NH + h)*NSEQ + n)*256 + d4];
            s.x += v.x; s.y += v.y; s.z += v.z; s.w += v.w;
        }
        po[idx] = s;
    }
}

// ---------------- launch ----------------
extern "C" void kernel_launch(void* const* d_in, const int* in_sizes, int n_in,
                              void* d_out, int out_size) {
    const float* x  = (const float*)d_in[0];
    const float* wq = (const float*)d_in[1];
    const float* wk = (const float*)d_in[2];
    const float* wg = (const float*)d_in[3];
    const float* ve = (const float*)d_in[4];
    const float* oe = (const float*)d_in[5];
    float* out = (float*)d_out;

    cudaFuncSetAttribute(attn_kernel,
                         cudaFuncAttributeMaxDynamicSharedMemorySize, ATTN2_SMEM);
    cudaFuncSetAttribute(projt_kernel,
                         cudaFuncAttributeMaxDynamicSharedMemorySize, TENS_SMEM);
    cudaFuncSetAttribute(valt_kernel,
                         cudaFuncAttributeMaxDynamicSharedMemorySize, TENS_SMEM);
    cudaFuncSetAttribute(outt_kernel,
                         cudaFuncAttributeMaxDynamicSharedMemorySize, TENS_SMEM);

    init_kernel<<<1, 64>>>();
    projt_kernel<<<dim3(TTOK/128, 16), 256, TENS_SMEM>>>(x, wq, wk);
    glogit_kernel<<<dim3(TTOK/128, 8), 256>>>(x, wg);
    gate_kernel<<<(TTOK*NH)/256, 256>>>();
    valt_kernel<<<dim3(NH*NE, TTOK/128), 256, TENS_SMEM>>>(x, ve);
    attn_kernel<<<dim3(BH, NSEQ/128), 256, ATTN2_SMEM>>>();
    outt_kernel<<<dim3(NH*NE, TTOK/128, DIMM/256), 256, TENS_SMEM>>>(oe);
    reduce_kernel<<<2048, 256>>>(out);
}